// round 7
// baseline (speedup 1.0000x reference)
#include <cuda_runtime.h>
#include <cuda_fp16.h>
#include <math.h>
#include <cstdint>

#define NTOK 4096
#define DDIM 512
#define HDIM 2048
#define NEXP 8
#define NC 7
#define BETA_FIXED (1.0f/3.0f)
#define BETA_DYN   (2.0f/3.0f)

// ================= scratch (static device globals) =================
__device__ __half g_xa[NTOK * DDIM];                 // activations fp16
__device__ __half g_w1[NEXP * HDIM * DDIM];          // [E][H][D] K-major fp16
__device__ __half g_w2[NEXP * DDIM * HDIM];          // [E][D][H] K-major fp16
__device__ __half g_ha[(size_t)NEXP * NTOK * HDIM];  // hidden fp16
__device__ float g_Y[(size_t)NEXP * NTOK * DDIM];
__device__ int   g_list[NEXP * NTOK];
__device__ float g_scale[NEXP * NTOK];
__device__ int   g_pos[NTOK * 2];
__device__ int   g_cnt[NEXP];
__device__ float g_imp[NC];

// ================= helpers =================
__device__ __forceinline__ uint32_t smem_u32(const void* p) {
    uint32_t a;
    asm("{ .reg .u64 t; cvta.to.shared.u64 t, %1; cvt.u32.u64 %0, t; }" : "=r"(a) : "l"(p));
    return a;
}
__device__ __forceinline__ void cpa16(uint32_t dst, const void* src) {
    asm volatile("cp.async.cg.shared.global [%0], [%1], 16;" :: "r"(dst), "l"(src));
}
#define CPA_COMMIT() asm volatile("cp.async.commit_group;" ::: "memory")
#define CPA_WAIT2()  asm volatile("cp.async.wait_group 2;" ::: "memory")

__device__ __forceinline__ void ldm_x4(uint32_t addr, uint32_t* r) {
    asm volatile("ldmatrix.sync.aligned.m8n8.x4.shared.b16 {%0,%1,%2,%3}, [%4];"
        : "=r"(r[0]), "=r"(r[1]), "=r"(r[2]), "=r"(r[3]) : "r"(addr));
}
__device__ __forceinline__ void mma16816(float* c, const uint32_t* a, uint32_t b0, uint32_t b1) {
    asm volatile("mma.sync.aligned.m16n8k16.row.col.f32.f16.f16.f32 "
        "{%0,%1,%2,%3}, {%4,%5,%6,%7}, {%8,%9}, {%0,%1,%2,%3};"
        : "+f"(c[0]), "+f"(c[1]), "+f"(c[2]), "+f"(c[3])
        : "r"(a[0]), "r"(a[1]), "r"(a[2]), "r"(a[3]), "r"(b0), "r"(b1));
}
__device__ __forceinline__ uint32_t pack2h(__half a, __half b) {
    return ((uint32_t)__half_as_ushort(b) << 16) | __half_as_ushort(a);
}

// smem per stage: A | B, each 128 rows x 80B (64B data = 32 fp16, +16B pad)
#define RSB 80
#define HALF_BYTES (128 * RSB)        // 10240
#define OFF_A  0
#define OFF_B  (1 * HALF_BYTES)
#define STAGE_BYTES (2 * HALF_BYTES)  // 20480
#define NSTG 4
#define SM_TILES 1024
#define SMEM_BYTES (SM_TILES + NSTG * STAGE_BYTES)   // 82944 -> 2 CTAs/SM

// ================= init =================
__global__ void k_init() {
    int t = threadIdx.x;
    if (t < NEXP) g_cnt[t] = 0;
    if (t < NC)   g_imp[t] = 0.f;
}

// ================= router =================
__global__ void k_router(const float* __restrict__ x,
                         const float* __restrict__ rW,
                         const float* __restrict__ rb,
                         float* __restrict__ out, long out_size) {
    __shared__ float imp_s[NC];
    int t = threadIdx.x;
    if (t < NC) imp_s[t] = 0.f;
    __syncthreads();

    int w = t >> 5, lane = t & 31;
    int n = blockIdx.x * 8 + w;

    float acc[NC];
#pragma unroll
    for (int j = 0; j < NC; j++) acc[j] = 0.f;

    const float* xr = x + (size_t)n * DDIM;
    for (int k = lane; k < DDIM; k += 32) {
        float xv = xr[k];
        const float* wr = rW + (size_t)k * NC;
#pragma unroll
        for (int j = 0; j < NC; j++) acc[j] += xv * wr[j];
    }
#pragma unroll
    for (int j = 0; j < NC; j++) {
#pragma unroll
        for (int off = 16; off > 0; off >>= 1)
            acc[j] += __shfl_xor_sync(0xffffffffu, acc[j], off);
        acc[j] += rb[j];
    }

    if (lane == 0) {
        float m = acc[0];
#pragma unroll
        for (int j = 1; j < NC; j++) m = fmaxf(m, acc[j]);
        float p[NC], s = 0.f;
#pragma unroll
        for (int j = 0; j < NC; j++) { p[j] = __expf(acc[j] - m); s += p[j]; }
        float inv = 1.f / s;
#pragma unroll
        for (int j = 0; j < NC; j++) atomicAdd(&imp_s[j], p[j] * inv);

        int i1 = 0;
#pragma unroll
        for (int j = 1; j < NC; j++) if (acc[j] > acc[i1]) i1 = j;
        int i2 = (i1 == 0) ? 1 : 0;
#pragma unroll
        for (int j = 0; j < NC; j++) if (j != i1 && acc[j] > acc[i2]) i2 = j;

        float e2 = __expf(acc[i2] - acc[i1]);
        float den = 1.f / (1.f + e2);
        float gA = den, gB = e2 * den;

        int eA = i1 + 1, eB = i2 + 1;
        int rA = atomicAdd(&g_cnt[eA], 1);
        int rB = atomicAdd(&g_cnt[eB], 1);
        int rowA = eA * NTOK + rA;
        int rowB = eB * NTOK + rB;
        g_list[rowA] = n;  g_list[rowB] = n;
        g_scale[rowA] = BETA_DYN * gA;
        g_scale[rowB] = BETA_DYN * gB;
        g_pos[2 * n]     = rowA;
        g_pos[2 * n + 1] = rowB;

        long selbase = (long)NTOK * DDIM + 2;
        if (selbase + 2 * (long)NTOK <= out_size) {
            out[selbase + 2 * n]     = (float)eA;
            out[selbase + 2 * n + 1] = (float)eB;
        }
    }
    __syncthreads();
    if (t < NC) atomicAdd(&g_imp[t], imp_s[t]);
}

__global__ void k_aux(float* __restrict__ out, long out_size) {
    float lbl = 0.f, ent = 0.f;
#pragma unroll
    for (int j = 0; j < NC; j++) {
        float imp = g_imp[j] / (float)NTOK;
        float d = imp - (1.0f / NC);
        lbl += d * d;
        ent -= imp * logf(fmaxf(imp, 1e-8f));
    }
    lbl *= (1.0f / NC);
    long base = (long)NTOK * DDIM;
    if (base < out_size)     out[base]     = lbl;
    if (base + 1 < out_size) out[base + 1] = ent;
}

// ================= conversions =================
__global__ void k_cvt_x(const float4* __restrict__ x) {
    int i = blockIdx.x * blockDim.x + threadIdx.x;
    float4 v = x[i];
    uint2 p;
    p.x = pack2h(__float2half(v.x), __float2half(v.y));
    p.y = pack2h(__float2half(v.z), __float2half(v.w));
    ((uint2*)g_xa)[i] = p;
}

// in [E][R][C] f32 -> out [E][C][R] fp16; which: 0=W1, 1=W2
__global__ void k_cvt_tr(const float* __restrict__ in, int R, int C, int which) {
    __shared__ float tile[32][33];
    int e = blockIdx.z;
    int c0 = blockIdx.x * 32, r0 = blockIdx.y * 32;
    int tx = threadIdx.x, ty = threadIdx.y;   // 32 x 8
    const float* ip = in + (size_t)e * R * C;
#pragma unroll
    for (int i = 0; i < 4; i++)
        tile[ty + 8 * i][tx] = ip[(size_t)(r0 + ty + 8 * i) * C + c0 + tx];
    __syncthreads();
    __half* oh = which ? g_w2 : g_w1;
#pragma unroll
    for (int i = 0; i < 4; i++) {
        float v = tile[tx][ty + 8 * i];
        size_t o = ((size_t)e * C + c0 + ty + 8 * i) * R + r0 + tx;
        oh[o] = __float2half(v);
    }
}

// ================= shared GEMM compute core =================
// block 128x128, 8 warps (2Mx4N), warp tile 64x32, k-chunk 32 (2 x k16)
__device__ __forceinline__ void gemm_compute_chunk(
    uint32_t tb, int wm, int wn, int lane, float acc[4][4][4])
{
    uint32_t a_row = (uint32_t)((lane & 7) + ((lane >> 3) & 1) * 8);
    uint32_t a_kh  = (uint32_t)(lane >> 4);
    uint32_t a_base = tb + OFF_A + (wm * 64 + a_row) * RSB + a_kh * 16;
    uint32_t b_base = tb + OFF_B + (wn * 32 + lane) * RSB;

#pragma unroll
    for (int kk = 0; kk < 2; kk++) {
        uint32_t ah[4][4];
#pragma unroll
        for (int mf = 0; mf < 4; mf++)
            ldm_x4(a_base + mf * 16 * RSB + kk * 32, ah[mf]);
        uint32_t b0[4], b1[4];
        ldm_x4(b_base + kk * 32,      b0);
        ldm_x4(b_base + kk * 32 + 16, b1);

#pragma unroll
        for (int mi = 0; mi < 4; mi++)
#pragma unroll
            for (int ni = 0; ni < 4; ni++)
                mma16816(acc[mi][ni], ah[mi], b0[ni], b1[ni]);
    }
}

// ================= GEMM 1: H = relu(Xg @ W1t[e] + b1[e]) -> fp16 =================
__global__ void __launch_bounds__(256, 2) k_gemm1(const float* __restrict__ b1) {
    int s = blockIdx.z;
    int cnt = (s == 0) ? NTOK : g_cnt[s];
    int m0 = blockIdx.x * 128;
    if (m0 >= cnt) return;
    int n0 = blockIdx.y * 128;

    extern __shared__ char smem[];
    uint32_t sb = smem_u32(smem);
    int t = threadIdx.x;
    int wid = t >> 5, lane = t & 31;
    int wm = wid >> 2, wn = wid & 3;
    int* toks = (int*)smem;

    if (t < 128) {
        int m = m0 + t;
        toks[t] = (m < cnt) ? ((s == 0) ? m : g_list[s * NTOK + m]) : 0;
    }
    __syncthreads();

    auto load_chunk = [&](int st, int k0) {
        uint32_t base = sb + SM_TILES + st * STAGE_BYTES;
#pragma unroll
        for (int i = 0; i < 2; i++) {
            int id = i * 256 + t;          // 0..511
            int row = id >> 2, seg = id & 3;
            uint32_t d = base + row * RSB + seg * 16;
            size_t aoff = (size_t)toks[row] * DDIM + k0 + seg * 8;
            cpa16(d + OFF_A, g_xa + aoff);
            size_t boff = ((size_t)s * HDIM + n0 + row) * DDIM + k0 + seg * 8;
            cpa16(d + OFF_B, g_w1 + boff);
        }
        CPA_COMMIT();
    };

    float acc[4][4][4];
#pragma unroll
    for (int mi = 0; mi < 4; mi++)
#pragma unroll
        for (int ni = 0; ni < 4; ni++)
#pragma unroll
            for (int q = 0; q < 4; q++) acc[mi][ni][q] = 0.f;

    const int CH = DDIM / 32;   // 16
    load_chunk(0, 0);
    load_chunk(1, 32);
    load_chunk(2, 64);
    for (int c = 0; c < CH; c++) {
        CPA_WAIT2();
        __syncthreads();
        if (c + 3 < CH) load_chunk((c + 3) & (NSTG - 1), (c + 3) * 32);
        else            CPA_COMMIT();   // keep group accounting uniform
        gemm_compute_chunk(sb + SM_TILES + (c & (NSTG - 1)) * STAGE_BYTES, wm, wn, lane, acc);
    }

    // epilogue: bias + relu -> fp16
    const float* bp = b1 + (size_t)s * HDIM;
#pragma unroll
    for (int mi = 0; mi < 4; mi++) {
        int mA = m0 + wm * 64 + mi * 16 + (lane >> 2);
        int mB = mA + 8;
        size_t rA = ((size_t)s * NTOK + mA) * HDIM;
        size_t rB = ((size_t)s * NTOK + mB) * HDIM;
        bool vA = mA < cnt, vB = mB < cnt;
#pragma unroll
        for (int ni = 0; ni < 4; ni++) {
            int col = n0 + wn * 32 + ni * 8 + 2 * (lane & 3);
            float bc0 = __ldg(bp + col), bc1 = __ldg(bp + col + 1);
            if (vA) {
                float v0 = fmaxf(acc[mi][ni][0] + bc0, 0.f);
                float v1 = fmaxf(acc[mi][ni][1] + bc1, 0.f);
                *(uint32_t*)(g_ha + rA + col) = pack2h(__float2half(v0), __float2half(v1));
            }
            if (vB) {
                float v0 = fmaxf(acc[mi][ni][2] + bc0, 0.f);
                float v1 = fmaxf(acc[mi][ni][3] + bc1, 0.f);
                *(uint32_t*)(g_ha + rB + col) = pack2h(__float2half(v0), __float2half(v1));
            }
        }
    }
}

// ================= GEMM 2: Y = scale * (H @ W2t[e] + b2[e]) =================
__global__ void __launch_bounds__(256, 2) k_gemm2(const float* __restrict__ b2,
                                                  const float* __restrict__ fw) {
    int s = blockIdx.z;
    int cnt = (s == 0) ? NTOK : g_cnt[s];
    int m0 = blockIdx.x * 128;
    if (m0 >= cnt) return;
    int n0 = blockIdx.y * 128;

    extern __shared__ char smem[];
    uint32_t sb = smem_u32(smem);
    int t = threadIdx.x;
    int wid = t >> 5, lane = t & 31;
    int wm = wid >> 2, wn = wid & 3;
    float* scl = (float*)smem;

    if (t < 128) {
        int m = m0 + t;
        scl[t] = (m < cnt) ? ((s == 0) ? BETA_FIXED * fw[0] : g_scale[s * NTOK + m]) : 0.f;
    }
    __syncthreads();

    auto load_chunk = [&](int st, int k0) {
        uint32_t base = sb + SM_TILES + st * STAGE_BYTES;
#pragma unroll
        for (int i = 0; i < 2; i++) {
            int id = i * 256 + t;
            int row = id >> 2, seg = id & 3;
            uint32_t d = base + row * RSB + seg * 16;
            size_t aoff = ((size_t)s * NTOK + m0 + row) * HDIM + k0 + seg * 8;
            cpa16(d + OFF_A, g_ha + aoff);
            size_t boff = ((size_t)s * DDIM + n0 + row) * HDIM + k0 + seg * 8;
            cpa16(d + OFF_B, g_w2 + boff);
        }
        CPA_COMMIT();
    };

    float acc[4][4][4];
#pragma unroll
    for (int mi = 0; mi < 4; mi++)
#pragma unroll
        for (int ni = 0; ni < 4; ni++)
#pragma unroll
            for (int q = 0; q < 4; q++) acc[mi][ni][q] = 0.f;

    const int CH = HDIM / 32;   // 64
    load_chunk(0, 0);
    load_chunk(1, 32);
    load_chunk(2, 64);
    for (int c = 0; c < CH; c++) {
        CPA_WAIT2();
        __syncthreads();
        if (c + 3 < CH) load_chunk((c + 3) & (NSTG - 1), (c + 3) * 32);
        else            CPA_COMMIT();
        gemm_compute_chunk(sb + SM_TILES + (c & (NSTG - 1)) * STAGE_BYTES, wm, wn, lane, acc);
    }

    // epilogue: (acc + bias) * scale, fp32 store
    const float* bp = b2 + (size_t)s * DDIM;
#pragma unroll
    for (int mi = 0; mi < 4; mi++) {
        int mloc = wm * 64 + mi * 16 + (lane >> 2);
        int mA = m0 + mloc, mB = mA + 8;
        float scA = scl[mloc], scB = scl[mloc + 8];
        size_t rA = ((size_t)s * NTOK + mA) * DDIM;
        size_t rB = ((size_t)s * NTOK + mB) * DDIM;
        bool vA = mA < cnt, vB = mB < cnt;
#pragma unroll
        for (int ni = 0; ni < 4; ni++) {
            int col = n0 + wn * 32 + ni * 8 + 2 * (lane & 3);
            float bc0 = __ldg(bp + col), bc1 = __ldg(bp + col + 1);
            if (vA) {
                float2 v;
                v.x = (acc[mi][ni][0] + bc0) * scA;
                v.y = (acc[mi][ni][1] + bc1) * scA;
                *(float2*)(g_Y + rA + col) = v;
            }
            if (vB) {
                float2 v;
                v.x = (acc[mi][ni][2] + bc0) * scB;
                v.y = (acc[mi][ni][3] + bc1) * scB;
                *(float2*)(g_Y + rB + col) = v;
            }
        }
    }
}

// ================= combine =================
__global__ void k_combine(float* __restrict__ out) {
    int n = blockIdx.x;
    int t = threadIdx.x;
    const float4* y0 = (const float4*)(g_Y + (size_t)n * DDIM);
    int pA = g_pos[2 * n], pB = g_pos[2 * n + 1];
    const float4* yA = (const float4*)(g_Y + (size_t)pA * DDIM);
    const float4* yB = (const float4*)(g_Y + (size_t)pB * DDIM);
    float4 a = y0[t], b = yA[t], c = yB[t];
    float4 r;
    r.x = a.x + b.x + c.x;
    r.y = a.y + b.y + c.y;
    r.z = a.z + b.z + c.z;
    r.w = a.w + b.w + c.w;
    ((float4*)(out + (size_t)n * DDIM))[t] = r;
}

// ================= launch =================
extern "C" void kernel_launch(void* const* d_in, const int* in_sizes, int n_in,
                              void* d_out, int out_size) {
    const float* x  = (const float*)d_in[0];
    const float* rW = (const float*)d_in[1];
    const float* rb = (const float*)d_in[2];
    const float* W1 = (const float*)d_in[3];
    const float* b1 = (const float*)d_in[4];
    const float* W2 = (const float*)d_in[5];
    const float* b2 = (const float*)d_in[6];
    const float* fw = (const float*)d_in[7];
    float* out = (float*)d_out;
    long osz = (long)out_size;

    cudaFuncSetAttribute(k_gemm1, cudaFuncAttributeMaxDynamicSharedMemorySize, SMEM_BYTES);
    cudaFuncSetAttribute(k_gemm2, cudaFuncAttributeMaxDynamicSharedMemorySize, SMEM_BYTES);

    k_init<<<1, 32>>>();
    k_router<<<NTOK / 8, 256>>>(x, rW, rb, out, osz);
    k_aux<<<1, 1>>>(out, osz);
    k_cvt_x<<<(NTOK * DDIM / 4) / 256, 256>>>((const float4*)x);
    k_cvt_tr<<<dim3(HDIM / 32, DDIM / 32, NEXP), dim3(32, 8)>>>(W1, DDIM, HDIM, 0);
    k_cvt_tr<<<dim3(DDIM / 32, HDIM / 32, NEXP), dim3(32, 8)>>>(W2, HDIM, DDIM, 1);
    k_gemm1<<<dim3(32, 16, 8), 256, SMEM_BYTES>>>(b1);
    k_gemm2<<<dim3(32, 4, 8), 256, SMEM_BYTES>>>(b2, fw);
    k_combine<<<NTOK, 128>>>(out);
}

// round 8
// speedup vs baseline: 1.0089x; 1.0089x over previous
#include <cuda_runtime.h>
#include <cuda_fp16.h>
#include <math.h>
#include <cstdint>

#define NTOK 4096
#define DDIM 512
#define HDIM 2048
#define NEXP 8
#define NC 7
#define BETA_FIXED (1.0f/3.0f)
#define BETA_DYN   (2.0f/3.0f)

// ================= scratch (static device globals) =================
__device__ __half g_xa[NTOK * DDIM];                 // activations fp16
__device__ __half g_w1[NEXP * HDIM * DDIM];          // [E][H][D] K-major fp16
__device__ __half g_w2[NEXP * DDIM * HDIM];          // [E][D][H] K-major fp16
__device__ __half g_ha[(size_t)NEXP * NTOK * HDIM];  // hidden fp16
__device__ float g_Y[(size_t)NEXP * NTOK * DDIM];
__device__ int   g_list[NEXP * NTOK];
__device__ float g_scale[NEXP * NTOK];
__device__ int   g_pos[NTOK * 2];
__device__ int   g_cnt[NEXP];
__device__ float g_imp[NC];

// ================= helpers =================
__device__ __forceinline__ uint32_t smem_u32(const void* p) {
    uint32_t a;
    asm("{ .reg .u64 t; cvta.to.shared.u64 t, %1; cvt.u32.u64 %0, t; }" : "=r"(a) : "l"(p));
    return a;
}
__device__ __forceinline__ void cpa16(uint32_t dst, const void* src) {
    asm volatile("cp.async.cg.shared.global [%0], [%1], 16;" :: "r"(dst), "l"(src));
}
#define CPA_COMMIT() asm volatile("cp.async.commit_group;" ::: "memory")
#define CPA_WAIT2()  asm volatile("cp.async.wait_group 2;" ::: "memory")

__device__ __forceinline__ void ldm_x4(uint32_t addr, uint32_t* r) {
    asm volatile("ldmatrix.sync.aligned.m8n8.x4.shared.b16 {%0,%1,%2,%3}, [%4];"
        : "=r"(r[0]), "=r"(r[1]), "=r"(r[2]), "=r"(r[3]) : "r"(addr));
}
__device__ __forceinline__ void mma16816(float* c, const uint32_t* a, uint32_t b0, uint32_t b1) {
    asm volatile("mma.sync.aligned.m16n8k16.row.col.f32.f16.f16.f32 "
        "{%0,%1,%2,%3}, {%4,%5,%6,%7}, {%8,%9}, {%0,%1,%2,%3};"
        : "+f"(c[0]), "+f"(c[1]), "+f"(c[2]), "+f"(c[3])
        : "r"(a[0]), "r"(a[1]), "r"(a[2]), "r"(a[3]), "r"(b0), "r"(b1));
}
__device__ __forceinline__ uint32_t pack2h(__half a, __half b) {
    return ((uint32_t)__half_as_ushort(b) << 16) | __half_as_ushort(a);
}

// smem per stage: A (64 rows) | B (128 rows), 80B rows (64B data = 32 fp16, +16B pad)
#define RSB 80
#define BM 64
#define OFF_A  0
#define OFF_B  (BM * RSB)                    // 5120
#define STAGE_BYTES ((BM + 128) * RSB)       // 15360
#define NSTG 4
#define SM_TILES 1024
#define SMEM_BYTES (SM_TILES + NSTG * STAGE_BYTES)   // 62464 -> 2 CTAs/SM

// ================= init =================
__global__ void k_init() {
    int t = threadIdx.x;
    if (t < NEXP) g_cnt[t] = 0;
    if (t < NC)   g_imp[t] = 0.f;
}

// ================= router =================
__global__ void k_router(const float* __restrict__ x,
                         const float* __restrict__ rW,
                         const float* __restrict__ rb,
                         float* __restrict__ out, long out_size) {
    __shared__ float imp_s[NC];
    int t = threadIdx.x;
    if (t < NC) imp_s[t] = 0.f;
    __syncthreads();

    int w = t >> 5, lane = t & 31;
    int n = blockIdx.x * 8 + w;

    float acc[NC];
#pragma unroll
    for (int j = 0; j < NC; j++) acc[j] = 0.f;

    const float* xr = x + (size_t)n * DDIM;
    for (int k = lane; k < DDIM; k += 32) {
        float xv = xr[k];
        const float* wr = rW + (size_t)k * NC;
#pragma unroll
        for (int j = 0; j < NC; j++) acc[j] += xv * wr[j];
    }
#pragma unroll
    for (int j = 0; j < NC; j++) {
#pragma unroll
        for (int off = 16; off > 0; off >>= 1)
            acc[j] += __shfl_xor_sync(0xffffffffu, acc[j], off);
        acc[j] += rb[j];
    }

    if (lane == 0) {
        float m = acc[0];
#pragma unroll
        for (int j = 1; j < NC; j++) m = fmaxf(m, acc[j]);
        float p[NC], s = 0.f;
#pragma unroll
        for (int j = 0; j < NC; j++) { p[j] = __expf(acc[j] - m); s += p[j]; }
        float inv = 1.f / s;
#pragma unroll
        for (int j = 0; j < NC; j++) atomicAdd(&imp_s[j], p[j] * inv);

        int i1 = 0;
#pragma unroll
        for (int j = 1; j < NC; j++) if (acc[j] > acc[i1]) i1 = j;
        int i2 = (i1 == 0) ? 1 : 0;
#pragma unroll
        for (int j = 0; j < NC; j++) if (j != i1 && acc[j] > acc[i2]) i2 = j;

        float e2 = __expf(acc[i2] - acc[i1]);
        float den = 1.f / (1.f + e2);
        float gA = den, gB = e2 * den;

        int eA = i1 + 1, eB = i2 + 1;
        int rA = atomicAdd(&g_cnt[eA], 1);
        int rB = atomicAdd(&g_cnt[eB], 1);
        int rowA = eA * NTOK + rA;
        int rowB = eB * NTOK + rB;
        g_list[rowA] = n;  g_list[rowB] = n;
        g_scale[rowA] = BETA_DYN * gA;
        g_scale[rowB] = BETA_DYN * gB;
        g_pos[2 * n]     = rowA;
        g_pos[2 * n + 1] = rowB;

        long selbase = (long)NTOK * DDIM + 2;
        if (selbase + 2 * (long)NTOK <= out_size) {
            out[selbase + 2 * n]     = (float)eA;
            out[selbase + 2 * n + 1] = (float)eB;
        }
    }
    __syncthreads();
    if (t < NC) atomicAdd(&g_imp[t], imp_s[t]);
}

__global__ void k_aux(float* __restrict__ out, long out_size) {
    float lbl = 0.f, ent = 0.f;
#pragma unroll
    for (int j = 0; j < NC; j++) {
        float imp = g_imp[j] / (float)NTOK;
        float d = imp - (1.0f / NC);
        lbl += d * d;
        ent -= imp * logf(fmaxf(imp, 1e-8f));
    }
    lbl *= (1.0f / NC);
    long base = (long)NTOK * DDIM;
    if (base < out_size)     out[base]     = lbl;
    if (base + 1 < out_size) out[base + 1] = ent;
}

// ================= conversions =================
__global__ void k_cvt_x(const float4* __restrict__ x) {
    int i = blockIdx.x * blockDim.x + threadIdx.x;
    float4 v = x[i];
    uint2 p;
    p.x = pack2h(__float2half(v.x), __float2half(v.y));
    p.y = pack2h(__float2half(v.z), __float2half(v.w));
    ((uint2*)g_xa)[i] = p;
}

// in [E][R][C] f32 -> out [E][C][R] fp16; which: 0=W1, 1=W2
__global__ void k_cvt_tr(const float* __restrict__ in, int R, int C, int which) {
    __shared__ float tile[32][33];
    int e = blockIdx.z;
    int c0 = blockIdx.x * 32, r0 = blockIdx.y * 32;
    int tx = threadIdx.x, ty = threadIdx.y;   // 32 x 8
    const float* ip = in + (size_t)e * R * C;
#pragma unroll
    for (int i = 0; i < 4; i++)
        tile[ty + 8 * i][tx] = ip[(size_t)(r0 + ty + 8 * i) * C + c0 + tx];
    __syncthreads();
    __half* oh = which ? g_w2 : g_w1;
#pragma unroll
    for (int i = 0; i < 4; i++) {
        float v = tile[tx][ty + 8 * i];
        size_t o = ((size_t)e * C + c0 + ty + 8 * i) * R + r0 + tx;
        oh[o] = __float2half(v);
    }
}

// ================= shared GEMM compute core =================
// block 64x128, 8 warps (2Mx4N), warp tile 32x32, k-chunk 32 (2 x k16)
__device__ __forceinline__ void gemm_compute_chunk(
    uint32_t tb, int wm, int wn, int lane, float acc[2][4][4])
{
    uint32_t a_row = (uint32_t)((lane & 7) + ((lane >> 3) & 1) * 8);
    uint32_t a_kh  = (uint32_t)(lane >> 4);
    uint32_t a_base = tb + OFF_A + (wm * 32 + a_row) * RSB + a_kh * 16;
    uint32_t b_base = tb + OFF_B + (wn * 32 + lane) * RSB;

#pragma unroll
    for (int kk = 0; kk < 2; kk++) {
        uint32_t ah[2][4];
#pragma unroll
        for (int mf = 0; mf < 2; mf++)
            ldm_x4(a_base + mf * 16 * RSB + kk * 32, ah[mf]);
        uint32_t b0[4], b1[4];
        ldm_x4(b_base + kk * 32,      b0);
        ldm_x4(b_base + kk * 32 + 16, b1);

#pragma unroll
        for (int mi = 0; mi < 2; mi++)
#pragma unroll
            for (int ni = 0; ni < 4; ni++)
                mma16816(acc[mi][ni], ah[mi], b0[ni], b1[ni]);
    }
}

// ================= GEMM 1: H = relu(Xg @ W1t[e] + b1[e]) -> fp16 =================
__global__ void __launch_bounds__(256, 2) k_gemm1(const float* __restrict__ b1) {
    int s = blockIdx.z;
    int cnt = (s == 0) ? NTOK : g_cnt[s];
    int m0 = blockIdx.x * BM;
    if (m0 >= cnt) return;
    int n0 = blockIdx.y * 128;

    extern __shared__ char smem[];
    uint32_t sb = smem_u32(smem);
    int t = threadIdx.x;
    int wid = t >> 5, lane = t & 31;
    int wm = wid >> 2, wn = wid & 3;
    int* toks = (int*)smem;

    if (t < BM) {
        int m = m0 + t;
        toks[t] = (m < cnt) ? ((s == 0) ? m : g_list[s * NTOK + m]) : 0;
    }
    __syncthreads();

    auto load_chunk = [&](int st, int k0) {
        uint32_t base = sb + SM_TILES + st * STAGE_BYTES;
        {   // A: 64 rows x 4 segs = 256 cp.async
            int row = t >> 2, seg = t & 3;
            uint32_t d = base + OFF_A + row * RSB + seg * 16;
            size_t aoff = (size_t)toks[row] * DDIM + k0 + seg * 8;
            cpa16(d, g_xa + aoff);
        }
#pragma unroll
        for (int i = 0; i < 2; i++) {   // B: 128 rows x 4 segs = 512 cp.async
            int id = i * 256 + t;
            int row = id >> 2, seg = id & 3;
            uint32_t d = base + OFF_B + row * RSB + seg * 16;
            size_t boff = ((size_t)s * HDIM + n0 + row) * DDIM + k0 + seg * 8;
            cpa16(d, g_w1 + boff);
        }
        CPA_COMMIT();
    };

    float acc[2][4][4];
#pragma unroll
    for (int mi = 0; mi < 2; mi++)
#pragma unroll
        for (int ni = 0; ni < 4; ni++)
#pragma unroll
            for (int q = 0; q < 4; q++) acc[mi][ni][q] = 0.f;

    const int CH = DDIM / 32;   // 16
    load_chunk(0, 0);
    load_chunk(1, 32);
    load_chunk(2, 64);
    for (int c = 0; c < CH; c++) {
        CPA_WAIT2();
        __syncthreads();
        if (c + 3 < CH) load_chunk((c + 3) & (NSTG - 1), (c + 3) * 32);
        else            CPA_COMMIT();   // keep group accounting uniform
        gemm_compute_chunk(sb + SM_TILES + (c & (NSTG - 1)) * STAGE_BYTES, wm, wn, lane, acc);
    }

    // epilogue: bias + relu -> fp16
    const float* bp = b1 + (size_t)s * HDIM;
#pragma unroll
    for (int mi = 0; mi < 2; mi++) {
        int mA = m0 + wm * 32 + mi * 16 + (lane >> 2);
        int mB = mA + 8;
        size_t rA = ((size_t)s * NTOK + mA) * HDIM;
        size_t rB = ((size_t)s * NTOK + mB) * HDIM;
        bool vA = mA < cnt, vB = mB < cnt;
#pragma unroll
        for (int ni = 0; ni < 4; ni++) {
            int col = n0 + wn * 32 + ni * 8 + 2 * (lane & 3);
            float bc0 = __ldg(bp + col), bc1 = __ldg(bp + col + 1);
            if (vA) {
                float v0 = fmaxf(acc[mi][ni][0] + bc0, 0.f);
                float v1 = fmaxf(acc[mi][ni][1] + bc1, 0.f);
                *(uint32_t*)(g_ha + rA + col) = pack2h(__float2half(v0), __float2half(v1));
            }
            if (vB) {
                float v0 = fmaxf(acc[mi][ni][2] + bc0, 0.f);
                float v1 = fmaxf(acc[mi][ni][3] + bc1, 0.f);
                *(uint32_t*)(g_ha + rB + col) = pack2h(__float2half(v0), __float2half(v1));
            }
        }
    }
}

// ================= GEMM 2: Y = scale * (H @ W2t[e] + b2[e]) =================
__global__ void __launch_bounds__(256, 2) k_gemm2(const float* __restrict__ b2,
                                                  const float* __restrict__ fw) {
    int s = blockIdx.z;
    int cnt = (s == 0) ? NTOK : g_cnt[s];
    int m0 = blockIdx.x * BM;
    if (m0 >= cnt) return;
    int n0 = blockIdx.y * 128;

    extern __shared__ char smem[];
    uint32_t sb = smem_u32(smem);
    int t = threadIdx.x;
    int wid = t >> 5, lane = t & 31;
    int wm = wid >> 2, wn = wid & 3;
    float* scl = (float*)smem;

    if (t < BM) {
        int m = m0 + t;
        scl[t] = (m < cnt) ? ((s == 0) ? BETA_FIXED * fw[0] : g_scale[s * NTOK + m]) : 0.f;
    }
    __syncthreads();

    auto load_chunk = [&](int st, int k0) {
        uint32_t base = sb + SM_TILES + st * STAGE_BYTES;
        {
            int row = t >> 2, seg = t & 3;
            uint32_t d = base + OFF_A + row * RSB + seg * 16;
            size_t aoff = ((size_t)s * NTOK + m0 + row) * HDIM + k0 + seg * 8;
            cpa16(d, g_ha + aoff);
        }
#pragma unroll
        for (int i = 0; i < 2; i++) {
            int id = i * 256 + t;
            int row = id >> 2, seg = id & 3;
            uint32_t d = base + OFF_B + row * RSB + seg * 16;
            size_t boff = ((size_t)s * DDIM + n0 + row) * HDIM + k0 + seg * 8;
            cpa16(d, g_w2 + boff);
        }
        CPA_COMMIT();
    };

    float acc[2][4][4];
#pragma unroll
    for (int mi = 0; mi < 2; mi++)
#pragma unroll
        for (int ni = 0; ni < 4; ni++)
#pragma unroll
            for (int q = 0; q < 4; q++) acc[mi][ni][q] = 0.f;

    const int CH = HDIM / 32;   // 64
    load_chunk(0, 0);
    load_chunk(1, 32);
    load_chunk(2, 64);
    for (int c = 0; c < CH; c++) {
        CPA_WAIT2();
        __syncthreads();
        if (c + 3 < CH) load_chunk((c + 3) & (NSTG - 1), (c + 3) * 32);
        else            CPA_COMMIT();
        gemm_compute_chunk(sb + SM_TILES + (c & (NSTG - 1)) * STAGE_BYTES, wm, wn, lane, acc);
    }

    // epilogue: (acc + bias) * scale, fp32 store
    const float* bp = b2 + (size_t)s * DDIM;
#pragma unroll
    for (int mi = 0; mi < 2; mi++) {
        int mloc = wm * 32 + mi * 16 + (lane >> 2);
        int mA = m0 + mloc, mB = mA + 8;
        float scA = scl[mloc], scB = scl[mloc + 8];
        size_t rA = ((size_t)s * NTOK + mA) * DDIM;
        size_t rB = ((size_t)s * NTOK + mB) * DDIM;
        bool vA = mA < cnt, vB = mB < cnt;
#pragma unroll
        for (int ni = 0; ni < 4; ni++) {
            int col = n0 + wn * 32 + ni * 8 + 2 * (lane & 3);
            float bc0 = __ldg(bp + col), bc1 = __ldg(bp + col + 1);
            if (vA) {
                float2 v;
                v.x = (acc[mi][ni][0] + bc0) * scA;
                v.y = (acc[mi][ni][1] + bc1) * scA;
                *(float2*)(g_Y + rA + col) = v;
            }
            if (vB) {
                float2 v;
                v.x = (acc[mi][ni][2] + bc0) * scB;
                v.y = (acc[mi][ni][3] + bc1) * scB;
                *(float2*)(g_Y + rB + col) = v;
            }
        }
    }
}

// ================= combine =================
__global__ void k_combine(float* __restrict__ out) {
    int n = blockIdx.x;
    int t = threadIdx.x;
    const float4* y0 = (const float4*)(g_Y + (size_t)n * DDIM);
    int pA = g_pos[2 * n], pB = g_pos[2 * n + 1];
    const float4* yA = (const float4*)(g_Y + (size_t)pA * DDIM);
    const float4* yB = (const float4*)(g_Y + (size_t)pB * DDIM);
    float4 a = y0[t], b = yA[t], c = yB[t];
    float4 r;
    r.x = a.x + b.x + c.x;
    r.y = a.y + b.y + c.y;
    r.z = a.z + b.z + c.z;
    r.w = a.w + b.w + c.w;
    ((float4*)(out + (size_t)n * DDIM))[t] = r;
}

// ================= launch =================
extern "C" void kernel_launch(void* const* d_in, const int* in_sizes, int n_in,
                              void* d_out, int out_size) {
    const float* x  = (const float*)d_in[0];
    const float* rW = (const float*)d_in[1];
    const float* rb = (const float*)d_in[2];
    const float* W1 = (const float*)d_in[3];
    const float* b1 = (const float*)d_in[4];
    const float* W2 = (const float*)d_in[5];
    const float* b2 = (const float*)d_in[6];
    const float* fw = (const float*)d_in[7];
    float* out = (float*)d_out;
    long osz = (long)out_size;

    cudaFuncSetAttribute(k_gemm1, cudaFuncAttributeMaxDynamicSharedMemorySize, SMEM_BYTES);
    cudaFuncSetAttribute(k_gemm2, cudaFuncAttributeMaxDynamicSharedMemorySize, SMEM_BYTES);

    k_init<<<1, 32>>>();
    k_router<<<NTOK / 8, 256>>>(x, rW, rb, out, osz);
    k_aux<<<1, 1>>>(out, osz);
    k_cvt_x<<<(NTOK * DDIM / 4) / 256, 256>>>((const float4*)x);
    k_cvt_tr<<<dim3(HDIM / 32, DDIM / 32, NEXP), dim3(32, 8)>>>(W1, DDIM, HDIM, 0);
    k_cvt_tr<<<dim3(DDIM / 32, HDIM / 32, NEXP), dim3(32, 8)>>>(W2, HDIM, DDIM, 1);
    k_gemm1<<<dim3(NTOK / BM, 16, 8), 256, SMEM_BYTES>>>(b1);
    k_gemm2<<<dim3(NTOK / BM, 4, 8), 256, SMEM_BYTES>>>(b2, fw);
    k_combine<<<NTOK, 128>>>(out);
}

// round 9
// speedup vs baseline: 1.0410x; 1.0318x over previous
#include <cuda_runtime.h>
#include <cuda_fp16.h>
#include <math.h>
#include <cstdint>

#define NTOK 4096
#define DDIM 512
#define HDIM 2048
#define NEXP 8
#define NC 7
#define BETA_FIXED (1.0f/3.0f)
#define BETA_DYN   (2.0f/3.0f)

// ================= scratch (static device globals) =================
__device__ __half g_xa[NTOK * DDIM];                 // activations fp16
__device__ __half g_w1[NEXP * HDIM * DDIM];          // [E][H][D] K-major fp16
__device__ __half g_w2[NEXP * DDIM * HDIM];          // [E][D][H] K-major fp16
__device__ __half g_ha[(size_t)NEXP * NTOK * HDIM];  // hidden fp16
__device__ float g_Y[(size_t)NEXP * NTOK * DDIM];
__device__ int   g_list[NEXP * NTOK];
__device__ float g_scale[NEXP * NTOK];
__device__ int   g_pos[NTOK * 2];
__device__ int   g_cnt[NEXP];
__device__ float g_imp[NC];

// ================= helpers =================
__device__ __forceinline__ uint32_t smem_u32(const void* p) {
    uint32_t a;
    asm("{ .reg .u64 t; cvta.to.shared.u64 t, %1; cvt.u32.u64 %0, t; }" : "=r"(a) : "l"(p));
    return a;
}
__device__ __forceinline__ void cpa16(uint32_t dst, const void* src) {
    asm volatile("cp.async.cg.shared.global [%0], [%1], 16;" :: "r"(dst), "l"(src));
}
#define CPA_COMMIT() asm volatile("cp.async.commit_group;" ::: "memory")
#define CPA_WAIT1()  asm volatile("cp.async.wait_group 1;" ::: "memory")

__device__ __forceinline__ void ldm_x4(uint32_t addr, uint32_t* r) {
    asm volatile("ldmatrix.sync.aligned.m8n8.x4.shared.b16 {%0,%1,%2,%3}, [%4];"
        : "=r"(r[0]), "=r"(r[1]), "=r"(r[2]), "=r"(r[3]) : "r"(addr));
}
__device__ __forceinline__ void mma16816(float* c, const uint32_t* a, uint32_t b0, uint32_t b1) {
    asm volatile("mma.sync.aligned.m16n8k16.row.col.f32.f16.f16.f32 "
        "{%0,%1,%2,%3}, {%4,%5,%6,%7}, {%8,%9}, {%0,%1,%2,%3};"
        : "+f"(c[0]), "+f"(c[1]), "+f"(c[2]), "+f"(c[3])
        : "r"(a[0]), "r"(a[1]), "r"(a[2]), "r"(a[3]), "r"(b0), "r"(b1));
}
__device__ __forceinline__ uint32_t pack2h(__half a, __half b) {
    return ((uint32_t)__half_as_ushort(b) << 16) | __half_as_ushort(a);
}

// smem per stage: A (64 rows) | B (128 rows), 144B rows (128B data = 64 fp16, +16B pad)
#define RSB 144
#define BM 64
#define OFF_A  0
#define OFF_B  (BM * RSB)                    // 9216
#define STAGE_BYTES ((BM + 128) * RSB)       // 27648
#define NSTG 3
#define SM_TILES 1024
#define SMEM_BYTES (SM_TILES + NSTG * STAGE_BYTES)   // 83968 -> 2 CTAs/SM

// ================= init =================
__global__ void k_init() {
    int t = threadIdx.x;
    if (t < NEXP) g_cnt[t] = 0;
    if (t < NC)   g_imp[t] = 0.f;
}

// ================= router (+ inline x -> fp16 conversion) =================
__global__ void k_router(const float* __restrict__ x,
                         const float* __restrict__ rW,
                         const float* __restrict__ rb,
                         float* __restrict__ out, long out_size) {
    __shared__ float imp_s[NC];
    int t = threadIdx.x;
    if (t < NC) imp_s[t] = 0.f;
    __syncthreads();

    int w = t >> 5, lane = t & 31;
    int n = blockIdx.x * 8 + w;

    float acc[NC];
#pragma unroll
    for (int j = 0; j < NC; j++) acc[j] = 0.f;

    const float* xr = x + (size_t)n * DDIM;
    __half* xout = g_xa + (size_t)n * DDIM;
    for (int k = lane; k < DDIM; k += 32) {
        float xv = xr[k];
        xout[k] = __float2half(xv);          // fused conversion
        const float* wr = rW + (size_t)k * NC;
#pragma unroll
        for (int j = 0; j < NC; j++) acc[j] += xv * wr[j];
    }
#pragma unroll
    for (int j = 0; j < NC; j++) {
#pragma unroll
        for (int off = 16; off > 0; off >>= 1)
            acc[j] += __shfl_xor_sync(0xffffffffu, acc[j], off);
        acc[j] += rb[j];
    }

    if (lane == 0) {
        float m = acc[0];
#pragma unroll
        for (int j = 1; j < NC; j++) m = fmaxf(m, acc[j]);
        float p[NC], s = 0.f;
#pragma unroll
        for (int j = 0; j < NC; j++) { p[j] = __expf(acc[j] - m); s += p[j]; }
        float inv = 1.f / s;
#pragma unroll
        for (int j = 0; j < NC; j++) atomicAdd(&imp_s[j], p[j] * inv);

        int i1 = 0;
#pragma unroll
        for (int j = 1; j < NC; j++) if (acc[j] > acc[i1]) i1 = j;
        int i2 = (i1 == 0) ? 1 : 0;
#pragma unroll
        for (int j = 0; j < NC; j++) if (j != i1 && acc[j] > acc[i2]) i2 = j;

        float e2 = __expf(acc[i2] - acc[i1]);
        float den = 1.f / (1.f + e2);
        float gA = den, gB = e2 * den;

        int eA = i1 + 1, eB = i2 + 1;
        int rA = atomicAdd(&g_cnt[eA], 1);
        int rB = atomicAdd(&g_cnt[eB], 1);
        int rowA = eA * NTOK + rA;
        int rowB = eB * NTOK + rB;
        g_list[rowA] = n;  g_list[rowB] = n;
        g_scale[rowA] = BETA_DYN * gA;
        g_scale[rowB] = BETA_DYN * gB;
        g_pos[2 * n]     = rowA;
        g_pos[2 * n + 1] = rowB;

        long selbase = (long)NTOK * DDIM + 2;
        if (selbase + 2 * (long)NTOK <= out_size) {
            out[selbase + 2 * n]     = (float)eA;
            out[selbase + 2 * n + 1] = (float)eB;
        }
    }
    __syncthreads();
    if (t < NC) atomicAdd(&g_imp[t], imp_s[t]);
}

// ================= conversions: weights transpose -> fp16 =================
// in [E][R][C] f32 -> out [E][C][R] fp16; which: 0=W1, 1=W2
__global__ void k_cvt_tr(const float* __restrict__ in, int R, int C, int which) {
    __shared__ float tile[32][33];
    int e = blockIdx.z;
    int c0 = blockIdx.x * 32, r0 = blockIdx.y * 32;
    int tx = threadIdx.x, ty = threadIdx.y;   // 32 x 8
    const float* ip = in + (size_t)e * R * C;
#pragma unroll
    for (int i = 0; i < 4; i++)
        tile[ty + 8 * i][tx] = ip[(size_t)(r0 + ty + 8 * i) * C + c0 + tx];
    __syncthreads();
    __half* oh = which ? g_w2 : g_w1;
#pragma unroll
    for (int i = 0; i < 4; i++) {
        float v = tile[tx][ty + 8 * i];
        size_t o = ((size_t)e * C + c0 + ty + 8 * i) * R + r0 + tx;
        oh[o] = __float2half(v);
    }
}

// ================= shared GEMM compute core =================
// block 64x128, 8 warps (2Mx4N), warp tile 32x32, k-chunk 64 (4 x k16)
__device__ __forceinline__ void gemm_compute_chunk(
    uint32_t tb, int wm, int wn, int lane, float acc[2][4][4])
{
    uint32_t a_row = (uint32_t)((lane & 7) + ((lane >> 3) & 1) * 8);
    uint32_t a_kh  = (uint32_t)(lane >> 4);
    uint32_t a_base = tb + OFF_A + (wm * 32 + a_row) * RSB + a_kh * 16;
    uint32_t b_base = tb + OFF_B + (wn * 32 + lane) * RSB;

#pragma unroll
    for (int kk = 0; kk < 4; kk++) {
        uint32_t ah[2][4];
#pragma unroll
        for (int mf = 0; mf < 2; mf++)
            ldm_x4(a_base + mf * 16 * RSB + kk * 32, ah[mf]);
        uint32_t b0[4], b1[4];
        ldm_x4(b_base + kk * 32,      b0);
        ldm_x4(b_base + kk * 32 + 16, b1);

#pragma unroll
        for (int mi = 0; mi < 2; mi++)
#pragma unroll
            for (int ni = 0; ni < 4; ni++)
                mma16816(acc[mi][ni], ah[mi], b0[ni], b1[ni]);
    }
}

// ================= GEMM 1: H = relu(Xg @ W1t[e] + b1[e]) -> fp16 =================
__global__ void __launch_bounds__(256, 2) k_gemm1(const float* __restrict__ b1) {
    int s = blockIdx.z;
    int cnt = (s == 0) ? NTOK : g_cnt[s];
    int m0 = blockIdx.x * BM;
    if (m0 >= cnt) return;
    int n0 = blockIdx.y * 128;

    extern __shared__ char smem[];
    uint32_t sb = smem_u32(smem);
    int t = threadIdx.x;
    int wid = t >> 5, lane = t & 31;
    int wm = wid >> 2, wn = wid & 3;
    int* toks = (int*)smem;

    if (t < BM) {
        int m = m0 + t;
        toks[t] = (m < cnt) ? ((s == 0) ? m : g_list[s * NTOK + m]) : 0;
    }
    __syncthreads();

    auto load_chunk = [&](int st, int k0) {
        uint32_t base = sb + SM_TILES + st * STAGE_BYTES;
#pragma unroll
        for (int i = 0; i < 2; i++) {   // A: 64 rows x 8 segs = 512 cp.async
            int id = i * 256 + t;
            int row = id >> 3, seg = id & 7;
            uint32_t d = base + OFF_A + row * RSB + seg * 16;
            size_t aoff = (size_t)toks[row] * DDIM + k0 + seg * 8;
            cpa16(d, g_xa + aoff);
        }
#pragma unroll
        for (int i = 0; i < 4; i++) {   // B: 128 rows x 8 segs = 1024 cp.async
            int id = i * 256 + t;
            int row = id >> 3, seg = id & 7;
            uint32_t d = base + OFF_B + row * RSB + seg * 16;
            size_t boff = ((size_t)s * HDIM + n0 + row) * DDIM + k0 + seg * 8;
            cpa16(d, g_w1 + boff);
        }
        CPA_COMMIT();
    };

    float acc[2][4][4];
#pragma unroll
    for (int mi = 0; mi < 2; mi++)
#pragma unroll
        for (int ni = 0; ni < 4; ni++)
#pragma unroll
            for (int q = 0; q < 4; q++) acc[mi][ni][q] = 0.f;

    const int CH = DDIM / 64;   // 8
    load_chunk(0, 0);
    load_chunk(1, 64);
    for (int c = 0; c < CH; c++) {
        CPA_WAIT1();
        __syncthreads();
        if (c + 2 < CH) load_chunk((c + 2) % NSTG, (c + 2) * 64);
        else            CPA_COMMIT();   // keep group accounting uniform
        gemm_compute_chunk(sb + SM_TILES + (c % NSTG) * STAGE_BYTES, wm, wn, lane, acc);
    }

    // epilogue: bias + relu -> fp16
    const float* bp = b1 + (size_t)s * HDIM;
#pragma unroll
    for (int mi = 0; mi < 2; mi++) {
        int mA = m0 + wm * 32 + mi * 16 + (lane >> 2);
        int mB = mA + 8;
        size_t rA = ((size_t)s * NTOK + mA) * HDIM;
        size_t rB = ((size_t)s * NTOK + mB) * HDIM;
        bool vA = mA < cnt, vB = mB < cnt;
#pragma unroll
        for (int ni = 0; ni < 4; ni++) {
            int col = n0 + wn * 32 + ni * 8 + 2 * (lane & 3);
            float bc0 = __ldg(bp + col), bc1 = __ldg(bp + col + 1);
            if (vA) {
                float v0 = fmaxf(acc[mi][ni][0] + bc0, 0.f);
                float v1 = fmaxf(acc[mi][ni][1] + bc1, 0.f);
                *(uint32_t*)(g_ha + rA + col) = pack2h(__float2half(v0), __float2half(v1));
            }
            if (vB) {
                float v0 = fmaxf(acc[mi][ni][2] + bc0, 0.f);
                float v1 = fmaxf(acc[mi][ni][3] + bc1, 0.f);
                *(uint32_t*)(g_ha + rB + col) = pack2h(__float2half(v0), __float2half(v1));
            }
        }
    }
}

// ================= GEMM 2: Y = scale * (H @ W2t[e] + b2[e]) =================
__global__ void __launch_bounds__(256, 2) k_gemm2(const float* __restrict__ b2,
                                                  const float* __restrict__ fw) {
    int s = blockIdx.z;
    int cnt = (s == 0) ? NTOK : g_cnt[s];
    int m0 = blockIdx.x * BM;
    if (m0 >= cnt) return;
    int n0 = blockIdx.y * 128;

    extern __shared__ char smem[];
    uint32_t sb = smem_u32(smem);
    int t = threadIdx.x;
    int wid = t >> 5, lane = t & 31;
    int wm = wid >> 2, wn = wid & 3;
    float* scl = (float*)smem;

    if (t < BM) {
        int m = m0 + t;
        scl[t] = (m < cnt) ? ((s == 0) ? BETA_FIXED * fw[0] : g_scale[s * NTOK + m]) : 0.f;
    }
    __syncthreads();

    auto load_chunk = [&](int st, int k0) {
        uint32_t base = sb + SM_TILES + st * STAGE_BYTES;
#pragma unroll
        for (int i = 0; i < 2; i++) {
            int id = i * 256 + t;
            int row = id >> 3, seg = id & 7;
            uint32_t d = base + OFF_A + row * RSB + seg * 16;
            size_t aoff = ((size_t)s * NTOK + m0 + row) * HDIM + k0 + seg * 8;
            cpa16(d, g_ha + aoff);
        }
#pragma unroll
        for (int i = 0; i < 4; i++) {
            int id = i * 256 + t;
            int row = id >> 3, seg = id & 7;
            uint32_t d = base + OFF_B + row * RSB + seg * 16;
            size_t boff = ((size_t)s * DDIM + n0 + row) * HDIM + k0 + seg * 8;
            cpa16(d, g_w2 + boff);
        }
        CPA_COMMIT();
    };

    float acc[2][4][4];
#pragma unroll
    for (int mi = 0; mi < 2; mi++)
#pragma unroll
        for (int ni = 0; ni < 4; ni++)
#pragma unroll
            for (int q = 0; q < 4; q++) acc[mi][ni][q] = 0.f;

    const int CH = HDIM / 64;   // 32
    load_chunk(0, 0);
    load_chunk(1, 64);
    for (int c = 0; c < CH; c++) {
        CPA_WAIT1();
        __syncthreads();
        if (c + 2 < CH) load_chunk((c + 2) % NSTG, (c + 2) * 64);
        else            CPA_COMMIT();
        gemm_compute_chunk(sb + SM_TILES + (c % NSTG) * STAGE_BYTES, wm, wn, lane, acc);
    }

    // epilogue: (acc + bias) * scale, fp32 store
    const float* bp = b2 + (size_t)s * DDIM;
#pragma unroll
    for (int mi = 0; mi < 2; mi++) {
        int mloc = wm * 32 + mi * 16 + (lane >> 2);
        int mA = m0 + mloc, mB = mA + 8;
        float scA = scl[mloc], scB = scl[mloc + 8];
        size_t rA = ((size_t)s * NTOK + mA) * DDIM;
        size_t rB = ((size_t)s * NTOK + mB) * DDIM;
        bool vA = mA < cnt, vB = mB < cnt;
#pragma unroll
        for (int ni = 0; ni < 4; ni++) {
            int col = n0 + wn * 32 + ni * 8 + 2 * (lane & 3);
            float bc0 = __ldg(bp + col), bc1 = __ldg(bp + col + 1);
            if (vA) {
                float2 v;
                v.x = (acc[mi][ni][0] + bc0) * scA;
                v.y = (acc[mi][ni][1] + bc1) * scA;
                *(float2*)(g_Y + rA + col) = v;
            }
            if (vB) {
                float2 v;
                v.x = (acc[mi][ni][2] + bc0) * scB;
                v.y = (acc[mi][ni][3] + bc1) * scB;
                *(float2*)(g_Y + rB + col) = v;
            }
        }
    }
}

// ================= combine (+ fused aux losses in block 0) =================
__global__ void k_combine(float* __restrict__ out, long out_size) {
    int n = blockIdx.x;
    int t = threadIdx.x;
    if (n == 0 && t == 0) {
        float lbl = 0.f, ent = 0.f;
#pragma unroll
        for (int j = 0; j < NC; j++) {
            float imp = g_imp[j] / (float)NTOK;
            float d = imp - (1.0f / NC);
            lbl += d * d;
            ent -= imp * logf(fmaxf(imp, 1e-8f));
        }
        lbl *= (1.0f / NC);
        long base = (long)NTOK * DDIM;
        if (base < out_size)     out[base]     = lbl;
        if (base + 1 < out_size) out[base + 1] = ent;
    }
    const float4* y0 = (const float4*)(g_Y + (size_t)n * DDIM);
    int pA = g_pos[2 * n], pB = g_pos[2 * n + 1];
    const float4* yA = (const float4*)(g_Y + (size_t)pA * DDIM);
    const float4* yB = (const float4*)(g_Y + (size_t)pB * DDIM);
    float4 a = y0[t], b = yA[t], c = yB[t];
    float4 r;
    r.x = a.x + b.x + c.x;
    r.y = a.y + b.y + c.y;
    r.z = a.z + b.z + c.z;
    r.w = a.w + b.w + c.w;
    ((float4*)(out + (size_t)n * DDIM))[t] = r;
}

// ================= launch =================
extern "C" void kernel_launch(void* const* d_in, const int* in_sizes, int n_in,
                              void* d_out, int out_size) {
    const float* x  = (const float*)d_in[0];
    const float* rW = (const float*)d_in[1];
    const float* rb = (const float*)d_in[2];
    const float* W1 = (const float*)d_in[3];
    const float* b1 = (const float*)d_in[4];
    const float* W2 = (const float*)d_in[5];
    const float* b2 = (const float*)d_in[6];
    const float* fw = (const float*)d_in[7];
    float* out = (float*)d_out;
    long osz = (long)out_size;

    cudaFuncSetAttribute(k_gemm1, cudaFuncAttributeMaxDynamicSharedMemorySize, SMEM_BYTES);
    cudaFuncSetAttribute(k_gemm2, cudaFuncAttributeMaxDynamicSharedMemorySize, SMEM_BYTES);

    k_init<<<1, 32>>>();
    k_router<<<NTOK / 8, 256>>>(x, rW, rb, out, osz);
    k_cvt_tr<<<dim3(HDIM / 32, DDIM / 32, NEXP), dim3(32, 8)>>>(W1, DDIM, HDIM, 0);
    k_cvt_tr<<<dim3(DDIM / 32, HDIM / 32, NEXP), dim3(32, 8)>>>(W2, HDIM, DDIM, 1);
    k_gemm1<<<dim3(NTOK / BM, 16, 8), 256, SMEM_BYTES>>>(b1);
    k_gemm2<<<dim3(NTOK / BM, 4, 8), 256, SMEM_BYTES>>>(b2, fw);
    k_combine<<<NTOK, 128>>>(out, osz);
}

// round 10
// speedup vs baseline: 1.0679x; 1.0259x over previous
#include <cuda_runtime.h>
#include <cuda_fp16.h>
#include <math.h>
#include <cstdint>

#define NTOK 4096
#define DDIM 512
#define HDIM 2048
#define NEXP 8
#define NC 7
#define BETA_FIXED (1.0f/3.0f)
#define BETA_DYN   (2.0f/3.0f)

// ================= scratch (static device globals) =================
__device__ __half g_xa[NTOK * DDIM];                 // activations fp16
__device__ __half g_w1[NEXP * DDIM * HDIM];          // [E][D][H] fp16 (same layout as input)
__device__ __half g_w2[NEXP * HDIM * DDIM];          // [E][H][D] fp16 (same layout as input)
__device__ __half g_ha[(size_t)NEXP * NTOK * HDIM];  // hidden fp16
__device__ float g_Y[(size_t)NEXP * NTOK * DDIM];
__device__ int   g_list[NEXP * NTOK];
__device__ float g_scale[NEXP * NTOK];
__device__ int   g_pos[NTOK * 2];
__device__ int   g_cnt[NEXP];    // zero at module load; k_combine re-zeroes after use
__device__ float g_imp[NC];      // idem

// ================= helpers =================
__device__ __forceinline__ uint32_t smem_u32(const void* p) {
    uint32_t a;
    asm("{ .reg .u64 t; cvta.to.shared.u64 t, %1; cvt.u32.u64 %0, t; }" : "=r"(a) : "l"(p));
    return a;
}
__device__ __forceinline__ void cpa16(uint32_t dst, const void* src) {
    asm volatile("cp.async.cg.shared.global [%0], [%1], 16;" :: "r"(dst), "l"(src));
}
#define CPA_COMMIT() asm volatile("cp.async.commit_group;" ::: "memory")
#define CPA_WAIT1()  asm volatile("cp.async.wait_group 1;" ::: "memory")

__device__ __forceinline__ void ldm_x4(uint32_t addr, uint32_t* r) {
    asm volatile("ldmatrix.sync.aligned.m8n8.x4.shared.b16 {%0,%1,%2,%3}, [%4];"
        : "=r"(r[0]), "=r"(r[1]), "=r"(r[2]), "=r"(r[3]) : "r"(addr));
}
__device__ __forceinline__ void ldm_x4t(uint32_t addr, uint32_t* r) {
    asm volatile("ldmatrix.sync.aligned.m8n8.x4.trans.shared.b16 {%0,%1,%2,%3}, [%4];"
        : "=r"(r[0]), "=r"(r[1]), "=r"(r[2]), "=r"(r[3]) : "r"(addr));
}
__device__ __forceinline__ void mma16816(float* c, const uint32_t* a, uint32_t b0, uint32_t b1) {
    asm volatile("mma.sync.aligned.m16n8k16.row.col.f32.f16.f16.f32 "
        "{%0,%1,%2,%3}, {%4,%5,%6,%7}, {%8,%9}, {%0,%1,%2,%3};"
        : "+f"(c[0]), "+f"(c[1]), "+f"(c[2]), "+f"(c[3])
        : "r"(a[0]), "r"(a[1]), "r"(a[2]), "r"(a[3]), "r"(b0), "r"(b1));
}
__device__ __forceinline__ uint32_t pack2h(__half a, __half b) {
    return ((uint32_t)__half_as_ushort(b) << 16) | __half_as_ushort(a);
}

// smem per stage:
//   A: BM=64 m-rows x 64 fp16 (128B data + 16B pad = 144B)
//   B: 64 k-rows x 128 fp16 n (256B data + 16B pad = 272B)
#define RSBA 144
#define RSBB 272
#define BM 64
#define OFF_A  0
#define OFF_B  (BM * RSBA)                       // 9216
#define STAGE_BYTES (BM * RSBA + 64 * RSBB)      // 26624
#define NSTG 3
#define SM_TILES 1024
#define SMEM_BYTES (SM_TILES + NSTG * STAGE_BYTES)   // 80896 -> 2 CTAs/SM

// ================= router (+ inline x -> fp16 conversion) =================
__global__ void k_router(const float* __restrict__ x,
                         const float* __restrict__ rW,
                         const float* __restrict__ rb,
                         float* __restrict__ out, long out_size) {
    __shared__ float imp_s[NC];
    int t = threadIdx.x;
    if (t < NC) imp_s[t] = 0.f;
    __syncthreads();

    int w = t >> 5, lane = t & 31;
    int n = blockIdx.x * 8 + w;

    float acc[NC];
#pragma unroll
    for (int j = 0; j < NC; j++) acc[j] = 0.f;

    const float* xr = x + (size_t)n * DDIM;
    __half* xout = g_xa + (size_t)n * DDIM;
    for (int k = lane; k < DDIM; k += 32) {
        float xv = xr[k];
        xout[k] = __float2half(xv);          // fused conversion
        const float* wr = rW + (size_t)k * NC;
#pragma unroll
        for (int j = 0; j < NC; j++) acc[j] += xv * wr[j];
    }
#pragma unroll
    for (int j = 0; j < NC; j++) {
#pragma unroll
        for (int off = 16; off > 0; off >>= 1)
            acc[j] += __shfl_xor_sync(0xffffffffu, acc[j], off);
        acc[j] += rb[j];
    }

    if (lane == 0) {
        float m = acc[0];
#pragma unroll
        for (int j = 1; j < NC; j++) m = fmaxf(m, acc[j]);
        float p[NC], s = 0.f;
#pragma unroll
        for (int j = 0; j < NC; j++) { p[j] = __expf(acc[j] - m); s += p[j]; }
        float inv = 1.f / s;
#pragma unroll
        for (int j = 0; j < NC; j++) atomicAdd(&imp_s[j], p[j] * inv);

        int i1 = 0;
#pragma unroll
        for (int j = 1; j < NC; j++) if (acc[j] > acc[i1]) i1 = j;
        int i2 = (i1 == 0) ? 1 : 0;
#pragma unroll
        for (int j = 0; j < NC; j++) if (j != i1 && acc[j] > acc[i2]) i2 = j;

        float e2 = __expf(acc[i2] - acc[i1]);
        float den = 1.f / (1.f + e2);
        float gA = den, gB = e2 * den;

        int eA = i1 + 1, eB = i2 + 1;
        int rA = atomicAdd(&g_cnt[eA], 1);
        int rB = atomicAdd(&g_cnt[eB], 1);
        int rowA = eA * NTOK + rA;
        int rowB = eB * NTOK + rB;
        g_list[rowA] = n;  g_list[rowB] = n;
        g_scale[rowA] = BETA_DYN * gA;
        g_scale[rowB] = BETA_DYN * gB;
        g_pos[2 * n]     = rowA;
        g_pos[2 * n + 1] = rowB;

        long selbase = (long)NTOK * DDIM + 2;
        if (selbase + 2 * (long)NTOK <= out_size) {
            out[selbase + 2 * n]     = (float)eA;
            out[selbase + 2 * n + 1] = (float)eB;
        }
    }
    __syncthreads();
    if (t < NC) atomicAdd(&g_imp[t], imp_s[t]);
}

// ================= weight convert: elementwise fp32 -> fp16 (no transpose) =====
#define W1_ELEMS (NEXP * DDIM * HDIM)
#define W2_ELEMS (NEXP * HDIM * DDIM)
__global__ void k_cvt_w(const float4* __restrict__ W1, const float4* __restrict__ W2) {
    int i = blockIdx.x * blockDim.x + threadIdx.x;      // over float4s
    const int T1 = W1_ELEMS / 4;
    float4 v;
    uint2 p;
    if (i < T1) {
        v = W1[i];
        p.x = pack2h(__float2half(v.x), __float2half(v.y));
        p.y = pack2h(__float2half(v.z), __float2half(v.w));
        ((uint2*)g_w1)[i] = p;
    } else {
        int j = i - T1;
        v = W2[j];
        p.x = pack2h(__float2half(v.x), __float2half(v.y));
        p.y = pack2h(__float2half(v.z), __float2half(v.w));
        ((uint2*)g_w2)[j] = p;
    }
}

// ================= shared GEMM compute core =================
// block 64x128, 8 warps (2Mx4N), warp tile 32x32, k-chunk 64 (4 x k16)
// A: [m][k] rows, non-trans ldmatrix.  B: [k][n] rows, trans ldmatrix.
__device__ __forceinline__ void gemm_compute_chunk(
    uint32_t tb, int wm, int wn, int lane, float acc[2][4][4])
{
    uint32_t a_row = (uint32_t)((lane & 7) + ((lane >> 3) & 1) * 8);
    uint32_t a_kh  = (uint32_t)(lane >> 4);
    uint32_t a_base = tb + OFF_A + (wm * 32 + a_row) * RSBA + a_kh * 16;

    // B trans pointers: grp = lane>>3 (matrix id), sub = lane&7 (k-row in matrix)
    uint32_t grp = (uint32_t)(lane >> 3), sub = (uint32_t)(lane & 7);
    uint32_t k_loc = (grp & 1) * 8 + sub;           // k row within k16
    uint32_t n_loc = (grp >> 1) * 8;                // n col within pair
    uint32_t b_base = tb + OFF_B + k_loc * RSBB + (wn * 32 + n_loc) * 2;

#pragma unroll
    for (int kk = 0; kk < 4; kk++) {
        uint32_t ah[2][4];
#pragma unroll
        for (int mf = 0; mf < 2; mf++)
            ldm_x4(a_base + mf * 16 * RSBA + kk * 32, ah[mf]);
#pragma unroll
        for (int pair = 0; pair < 2; pair++) {
            uint32_t br[4];
            // matrices: 0:(k0-7,nA) 1:(k8-15,nA) 2:(k0-7,nA+8) 3:(k8-15,nA+8)
            ldm_x4t(b_base + kk * 16 * RSBB + pair * 32, br);
#pragma unroll
            for (int q = 0; q < 2; q++) {
                int ni = pair * 2 + q;
#pragma unroll
                for (int mi = 0; mi < 2; mi++)
                    mma16816(acc[mi][ni], ah[mi], br[2 * q], br[2 * q + 1]);
            }
        }
    }
}

// ================= GEMM 1: H = relu(Xg @ W1[e] + b1[e]) -> fp16 =================
__global__ void __launch_bounds__(256, 2) k_gemm1(const float* __restrict__ b1) {
    int s = blockIdx.z;
    int cnt = (s == 0) ? NTOK : g_cnt[s];
    int m0 = blockIdx.x * BM;
    if (m0 >= cnt) return;
    int n0 = blockIdx.y * 128;

    extern __shared__ char smem[];
    uint32_t sb = smem_u32(smem);
    int t = threadIdx.x;
    int wid = t >> 5, lane = t & 31;
    int wm = wid >> 2, wn = wid & 3;
    int* toks = (int*)smem;

    if (t < BM) {
        int m = m0 + t;
        toks[t] = (m < cnt) ? ((s == 0) ? m : g_list[s * NTOK + m]) : 0;
    }
    __syncthreads();

    auto load_chunk = [&](int st, int k0) {
        uint32_t base = sb + SM_TILES + st * STAGE_BYTES;
#pragma unroll
        for (int i = 0; i < 2; i++) {   // A: 64 rows x 8 segs = 512 cp.async
            int id = i * 256 + t;
            int row = id >> 3, seg = id & 7;
            uint32_t d = base + OFF_A + row * RSBA + seg * 16;
            size_t aoff = (size_t)toks[row] * DDIM + k0 + seg * 8;
            cpa16(d, g_xa + aoff);
        }
#pragma unroll
        for (int i = 0; i < 4; i++) {   // B: 64 k-rows x 16 segs = 1024 cp.async
            int id = i * 256 + t;
            int row = id >> 4, seg = id & 15;
            uint32_t d = base + OFF_B + row * RSBB + seg * 16;
            size_t boff = ((size_t)s * DDIM + k0 + row) * HDIM + n0 + seg * 8;
            cpa16(d, g_w1 + boff);
        }
        CPA_COMMIT();
    };

    float acc[2][4][4];
#pragma unroll
    for (int mi = 0; mi < 2; mi++)
#pragma unroll
        for (int ni = 0; ni < 4; ni++)
#pragma unroll
            for (int q = 0; q < 4; q++) acc[mi][ni][q] = 0.f;

    const int CH = DDIM / 64;   // 8
    load_chunk(0, 0);
    load_chunk(1, 64);
    for (int c = 0; c < CH; c++) {
        CPA_WAIT1();
        __syncthreads();
        if (c + 2 < CH) load_chunk((c + 2) % NSTG, (c + 2) * 64);
        else            CPA_COMMIT();   // keep group accounting uniform
        gemm_compute_chunk(sb + SM_TILES + (c % NSTG) * STAGE_BYTES, wm, wn, lane, acc);
    }

    // epilogue: bias + relu -> fp16
    const float* bp = b1 + (size_t)s * HDIM;
#pragma unroll
    for (int mi = 0; mi < 2; mi++) {
        int mA = m0 + wm * 32 + mi * 16 + (lane >> 2);
        int mB = mA + 8;
        size_t rA = ((size_t)s * NTOK + mA) * HDIM;
        size_t rB = ((size_t)s * NTOK + mB) * HDIM;
        bool vA = mA < cnt, vB = mB < cnt;
#pragma unroll
        for (int ni = 0; ni < 4; ni++) {
            int col = n0 + wn * 32 + ni * 8 + 2 * (lane & 3);
            float bc0 = __ldg(bp + col), bc1 = __ldg(bp + col + 1);
            if (vA) {
                float v0 = fmaxf(acc[mi][ni][0] + bc0, 0.f);
                float v1 = fmaxf(acc[mi][ni][1] + bc1, 0.f);
                *(uint32_t*)(g_ha + rA + col) = pack2h(__float2half(v0), __float2half(v1));
            }
            if (vB) {
                float v0 = fmaxf(acc[mi][ni][2] + bc0, 0.f);
                float v1 = fmaxf(acc[mi][ni][3] + bc1, 0.f);
                *(uint32_t*)(g_ha + rB + col) = pack2h(__float2half(v0), __float2half(v1));
            }
        }
    }
}

// ================= GEMM 2: Y = scale * (H @ W2[e] + b2[e]) =================
__global__ void __launch_bounds__(256, 2) k_gemm2(const float* __restrict__ b2,
                                                  const float* __restrict__ fw) {
    int s = blockIdx.z;
    int cnt = (s == 0) ? NTOK : g_cnt[s];
    int m0 = blockIdx.x * BM;
    if (m0 >= cnt) return;
    int n0 = blockIdx.y * 128;

    extern __shared__ char smem[];
    uint32_t sb = smem_u32(smem);
    int t = threadIdx.x;
    int wid = t >> 5, lane = t & 31;
    int wm = wid >> 2, wn = wid & 3;
    float* scl = (float*)smem;

    if (t < BM) {
        int m = m0 + t;
        scl[t] = (m < cnt) ? ((s == 0) ? BETA_FIXED * fw[0] : g_scale[s * NTOK + m]) : 0.f;
    }
    __syncthreads();

    auto load_chunk = [&](int st, int k0) {
        uint32_t base = sb + SM_TILES + st * STAGE_BYTES;
#pragma unroll
        for (int i = 0; i < 2; i++) {
            int id = i * 256 + t;
            int row = id >> 3, seg = id & 7;
            uint32_t d = base + OFF_A + row * RSBA + seg * 16;
            size_t aoff = ((size_t)s * NTOK + m0 + row) * HDIM + k0 + seg * 8;
            cpa16(d, g_ha + aoff);
        }
#pragma unroll
        for (int i = 0; i < 4; i++) {
            int id = i * 256 + t;
            int row = id >> 4, seg = id & 15;
            uint32_t d = base + OFF_B + row * RSBB + seg * 16;
            size_t boff = ((size_t)s * HDIM + k0 + row) * DDIM + n0 + seg * 8;
            cpa16(d, g_w2 + boff);
        }
        CPA_COMMIT();
    };

    float acc[2][4][4];
#pragma unroll
    for (int mi = 0; mi < 2; mi++)
#pragma unroll
        for (int ni = 0; ni < 4; ni++)
#pragma unroll
            for (int q = 0; q < 4; q++) acc[mi][ni][q] = 0.f;

    const int CH = HDIM / 64;   // 32
    load_chunk(0, 0);
    load_chunk(1, 64);
    for (int c = 0; c < CH; c++) {
        CPA_WAIT1();
        __syncthreads();
        if (c + 2 < CH) load_chunk((c + 2) % NSTG, (c + 2) * 64);
        else            CPA_COMMIT();
        gemm_compute_chunk(sb + SM_TILES + (c % NSTG) * STAGE_BYTES, wm, wn, lane, acc);
    }

    // epilogue: (acc + bias) * scale, fp32 store
    const float* bp = b2 + (size_t)s * DDIM;
#pragma unroll
    for (int mi = 0; mi < 2; mi++) {
        int mloc = wm * 32 + mi * 16 + (lane >> 2);
        int mA = m0 + mloc, mB = mA + 8;
        float scA = scl[mloc], scB = scl[mloc + 8];
        size_t rA = ((size_t)s * NTOK + mA) * DDIM;
        size_t rB = ((size_t)s * NTOK + mB) * DDIM;
        bool vA = mA < cnt, vB = mB < cnt;
#pragma unroll
        for (int ni = 0; ni < 4; ni++) {
            int col = n0 + wn * 32 + ni * 8 + 2 * (lane & 3);
            float bc0 = __ldg(bp + col), bc1 = __ldg(bp + col + 1);
            if (vA) {
                float2 v;
                v.x = (acc[mi][ni][0] + bc0) * scA;
                v.y = (acc[mi][ni][1] + bc1) * scA;
                *(float2*)(g_Y + rA + col) = v;
            }
            if (vB) {
                float2 v;
                v.x = (acc[mi][ni][2] + bc0) * scB;
                v.y = (acc[mi][ni][3] + bc1) * scB;
                *(float2*)(g_Y + rB + col) = v;
            }
        }
    }
}

// ================= combine (+ fused aux losses, + counter re-zero) =================
__global__ void k_combine(float* __restrict__ out, long out_size) {
    int n = blockIdx.x;
    int t = threadIdx.x;
    if (n == 0 && t == 0) {
        float lbl = 0.f, ent = 0.f;
#pragma unroll
        for (int j = 0; j < NC; j++) {
            float imp = g_imp[j] / (float)NTOK;
            float d = imp - (1.0f / NC);
            lbl += d * d;
            ent -= imp * logf(fmaxf(imp, 1e-8f));
        }
        lbl *= (1.0f / NC);
        long base = (long)NTOK * DDIM;
        if (base < out_size)     out[base]     = lbl;
        if (base + 1 < out_size) out[base + 1] = ent;
        // leave counters zeroed for the next invocation (graph replay)
#pragma unroll
        for (int j = 0; j < NC; j++) g_imp[j] = 0.f;
#pragma unroll
        for (int j = 0; j < NEXP; j++) g_cnt[j] = 0;
    }
    const float4* y0 = (const float4*)(g_Y + (size_t)n * DDIM);
    int pA = g_pos[2 * n], pB = g_pos[2 * n + 1];
    const float4* yA = (const float4*)(g_Y + (size_t)pA * DDIM);
    const float4* yB = (const float4*)(g_Y + (size_t)pB * DDIM);
    float4 a = y0[t], b = yA[t], c = yB[t];
    float4 r;
    r.x = a.x + b.x + c.x;
    r.y = a.y + b.y + c.y;
    r.z = a.z + b.z + c.z;
    r.w = a.w + b.w + c.w;
    ((float4*)(out + (size_t)n * DDIM))[t] = r;
}

// ================= launch =================
extern "C" void kernel_launch(void* const* d_in, const int* in_sizes, int n_in,
                              void* d_out, int out_size) {
    const float* x  = (const float*)d_in[0];
    const float* rW = (const float*)d_in[1];
    const float* rb = (const float*)d_in[2];
    const float* W1 = (const float*)d_in[3];
    const float* b1 = (const float*)d_in[4];
    const float* W2 = (const float*)d_in[5];
    const float* b2 = (const float*)d_in[6];
    const float* fw = (const float*)d_in[7];
    float* out = (float*)d_out;
    long osz = (long)out_size;

    cudaFuncSetAttribute(k_gemm1, cudaFuncAttributeMaxDynamicSharedMemorySize, SMEM_BYTES);
    cudaFuncSetAttribute(k_gemm2, cudaFuncAttributeMaxDynamicSharedMemorySize, SMEM_BYTES);

    k_router<<<NTOK / 8, 256>>>(x, rW, rb, out, osz);
    k_cvt_w<<<(W1_ELEMS + W2_ELEMS) / 4 / 256, 256>>>((const float4*)W1, (const float4*)W2);
    k_gemm1<<<dim3(NTOK / BM, 16, 8), 256, SMEM_BYTES>>>(b1);
    k_gemm2<<<dim3(NTOK / BM, 4, 8), 256, SMEM_BYTES>>>(b2, fw);
    k_combine<<<NTOK, 128>>>(out, osz);
}

// round 11
// speedup vs baseline: 1.1475x; 1.0745x over previous
#include <cuda_runtime.h>
#include <cuda_fp16.h>
#include <math.h>
#include <cstdint>

#define NTOK 4096
#define DDIM 512
#define HDIM 2048
#define NEXP 8
#define NC 7
#define BETA_FIXED (1.0f/3.0f)
#define BETA_DYN   (2.0f/3.0f)

// ================= scratch (static device globals) =================
__device__ __half g_xa[NTOK * DDIM];                 // activations fp16
__device__ __half g_w1[NEXP * DDIM * HDIM];          // [E][D][H] fp16
__device__ __half g_w2[NEXP * HDIM * DDIM];          // [E][H][D] fp16
__device__ __half g_ha[(size_t)NEXP * NTOK * HDIM];  // hidden fp16
__device__ float g_Y[(size_t)NEXP * NTOK * DDIM];
__device__ int   g_list[NEXP * NTOK];
__device__ float g_scale[NEXP * NTOK];
__device__ int   g_pos[NTOK * 2];
__device__ int   g_cnt[NEXP];    // zero at module load; k_combine re-zeroes after use
__device__ float g_imp[NC];      // idem

// ================= helpers =================
__device__ __forceinline__ uint32_t smem_u32(const void* p) {
    uint32_t a;
    asm("{ .reg .u64 t; cvta.to.shared.u64 t, %1; cvt.u32.u64 %0, t; }" : "=r"(a) : "l"(p));
    return a;
}
__device__ __forceinline__ void cpa16(uint32_t dst, const void* src) {
    asm volatile("cp.async.cg.shared.global [%0], [%1], 16;" :: "r"(dst), "l"(src));
}
#define CPA_COMMIT() asm volatile("cp.async.commit_group;" ::: "memory")
#define CPA_WAIT0()  asm volatile("cp.async.wait_group 0;" ::: "memory")

__device__ __forceinline__ void ldm_x4(uint32_t addr, uint32_t* r) {
    asm volatile("ldmatrix.sync.aligned.m8n8.x4.shared.b16 {%0,%1,%2,%3}, [%4];"
        : "=r"(r[0]), "=r"(r[1]), "=r"(r[2]), "=r"(r[3]) : "r"(addr));
}
__device__ __forceinline__ void ldm_x4t(uint32_t addr, uint32_t* r) {
    asm volatile("ldmatrix.sync.aligned.m8n8.x4.trans.shared.b16 {%0,%1,%2,%3}, [%4];"
        : "=r"(r[0]), "=r"(r[1]), "=r"(r[2]), "=r"(r[3]) : "r"(addr));
}
__device__ __forceinline__ void mma16816(float* c, const uint32_t* a, uint32_t b0, uint32_t b1) {
    asm volatile("mma.sync.aligned.m16n8k16.row.col.f32.f16.f16.f32 "
        "{%0,%1,%2,%3}, {%4,%5,%6,%7}, {%8,%9}, {%0,%1,%2,%3};"
        : "+f"(c[0]), "+f"(c[1]), "+f"(c[2]), "+f"(c[3])
        : "r"(a[0]), "r"(a[1]), "r"(a[2]), "r"(a[3]), "r"(b0), "r"(b1));
}
__device__ __forceinline__ uint32_t pack2h(__half a, __half b) {
    return ((uint32_t)__half_as_ushort(b) << 16) | __half_as_ushort(a);
}

// smem per stage:
//   A: 128 m-rows x 64 fp16 k  (128B data + 16B pad = 144B)
//   B: 64 k-rows x 128 fp16 n  (256B data + 16B pad = 272B)
#define RSBA 144
#define RSBB 272
#define BM 128
#define OFF_A  0
#define OFF_B  (BM * RSBA)                       // 18432
#define STAGE_BYTES (BM * RSBA + 64 * RSBB)      // 35840
#define NSTG 2
#define SM_TILES 1024
#define SMEM_BYTES (SM_TILES + NSTG * STAGE_BYTES)   // 72704 -> 2 CTAs/SM

// ================= router (+ inline x -> fp16 conversion) =================
__global__ void k_router(const float* __restrict__ x,
                         const float* __restrict__ rW,
                         const float* __restrict__ rb,
                         float* __restrict__ out, long out_size) {
    __shared__ float imp_s[NC];
    int t = threadIdx.x;
    if (t < NC) imp_s[t] = 0.f;
    __syncthreads();

    int w = t >> 5, lane = t & 31;
    int n = blockIdx.x * 8 + w;

    float acc[NC];
#pragma unroll
    for (int j = 0; j < NC; j++) acc[j] = 0.f;

    const float* xr = x + (size_t)n * DDIM;
    __half* xout = g_xa + (size_t)n * DDIM;
    for (int k = lane; k < DDIM; k += 32) {
        float xv = xr[k];
        xout[k] = __float2half(xv);          // fused conversion
        const float* wr = rW + (size_t)k * NC;
#pragma unroll
        for (int j = 0; j < NC; j++) acc[j] += xv * wr[j];
    }
#pragma unroll
    for (int j = 0; j < NC; j++) {
#pragma unroll
        for (int off = 16; off > 0; off >>= 1)
            acc[j] += __shfl_xor_sync(0xffffffffu, acc[j], off);
        acc[j] += rb[j];
    }

    if (lane == 0) {
        float m = acc[0];
#pragma unroll
        for (int j = 1; j < NC; j++) m = fmaxf(m, acc[j]);
        float p[NC], s = 0.f;
#pragma unroll
        for (int j = 0; j < NC; j++) { p[j] = __expf(acc[j] - m); s += p[j]; }
        float inv = 1.f / s;
#pragma unroll
        for (int j = 0; j < NC; j++) atomicAdd(&imp_s[j], p[j] * inv);

        int i1 = 0;
#pragma unroll
        for (int j = 1; j < NC; j++) if (acc[j] > acc[i1]) i1 = j;
        int i2 = (i1 == 0) ? 1 : 0;
#pragma unroll
        for (int j = 0; j < NC; j++) if (j != i1 && acc[j] > acc[i2]) i2 = j;

        float e2 = __expf(acc[i2] - acc[i1]);
        float den = 1.f / (1.f + e2);
        float gA = den, gB = e2 * den;

        int eA = i1 + 1, eB = i2 + 1;
        int rA = atomicAdd(&g_cnt[eA], 1);
        int rB = atomicAdd(&g_cnt[eB], 1);
        int rowA = eA * NTOK + rA;
        int rowB = eB * NTOK + rB;
        g_list[rowA] = n;  g_list[rowB] = n;
        g_scale[rowA] = BETA_DYN * gA;
        g_scale[rowB] = BETA_DYN * gB;
        g_pos[2 * n]     = rowA;
        g_pos[2 * n + 1] = rowB;

        long selbase = (long)NTOK * DDIM + 2;
        if (selbase + 2 * (long)NTOK <= out_size) {
            out[selbase + 2 * n]     = (float)eA;
            out[selbase + 2 * n + 1] = (float)eB;
        }
    }
    __syncthreads();
    if (t < NC) atomicAdd(&g_imp[t], imp_s[t]);
}

// ================= weight convert: elementwise fp32 -> fp16 =================
#define W1_ELEMS (NEXP * DDIM * HDIM)
#define W2_ELEMS (NEXP * HDIM * DDIM)
__global__ void k_cvt_w(const float4* __restrict__ W1, const float4* __restrict__ W2) {
    int i = blockIdx.x * blockDim.x + threadIdx.x;      // over float4s
    const int T1 = W1_ELEMS / 4;
    float4 v;
    uint2 p;
    if (i < T1) {
        v = W1[i];
        p.x = pack2h(__float2half(v.x), __float2half(v.y));
        p.y = pack2h(__float2half(v.z), __float2half(v.w));
        ((uint2*)g_w1)[i] = p;
    } else {
        int j = i - T1;
        v = W2[j];
        p.x = pack2h(__float2half(v.x), __float2half(v.y));
        p.y = pack2h(__float2half(v.z), __float2half(v.w));
        ((uint2*)g_w2)[j] = p;
    }
}

// ================= shared GEMM compute core =================
// block 128x128, 4 warps (2Mx2N), warp tile 64x64, k-chunk 64 (4 x k16)
// A: [m][k] rows, non-trans ldmatrix.  B: [k][n] rows, trans ldmatrix.
__device__ __forceinline__ void gemm_compute_chunk(
    uint32_t tb, int wm, int wn, int lane, float acc[4][8][4])
{
    uint32_t a_row = (uint32_t)((lane & 7) + ((lane >> 3) & 1) * 8);
    uint32_t a_kh  = (uint32_t)(lane >> 4);
    uint32_t a_base = tb + OFF_A + (wm * 64 + a_row) * RSBA + a_kh * 16;

    uint32_t grp = (uint32_t)(lane >> 3), sub = (uint32_t)(lane & 7);
    uint32_t k_loc = (grp & 1) * 8 + sub;           // k row within k16
    uint32_t n_loc = (grp >> 1) * 8;                // n col within 16-col group
    uint32_t b_base = tb + OFF_B + k_loc * RSBB + (wn * 64 + n_loc) * 2;

#pragma unroll
    for (int kk = 0; kk < 4; kk++) {
        uint32_t ah[4][4];
#pragma unroll
        for (int mf = 0; mf < 4; mf++)
            ldm_x4(a_base + mf * 16 * RSBA + kk * 32, ah[mf]);
#pragma unroll
        for (int p = 0; p < 4; p++) {
            uint32_t br[4];
            ldm_x4t(b_base + kk * 16 * RSBB + p * 32, br);
#pragma unroll
            for (int q = 0; q < 2; q++) {
                int ni = p * 2 + q;
#pragma unroll
                for (int mi = 0; mi < 4; mi++)
                    mma16816(acc[mi][ni], ah[mi], br[2 * q], br[2 * q + 1]);
            }
        }
    }
}

// ================= GEMM 1: H = relu(Xg @ W1[e] + b1[e]) -> fp16 =================
__global__ void __launch_bounds__(128, 2) k_gemm1(const float* __restrict__ b1) {
    int s = blockIdx.z;
    int cnt = (s == 0) ? NTOK : g_cnt[s];
    int m0 = blockIdx.x * BM;
    if (m0 >= cnt) return;
    int n0 = blockIdx.y * 128;

    extern __shared__ char smem[];
    uint32_t sb = smem_u32(smem);
    int t = threadIdx.x;
    int wid = t >> 5, lane = t & 31;
    int wm = wid >> 1, wn = wid & 1;
    int* toks = (int*)smem;

    {
        int m = m0 + t;
        toks[t] = (m < cnt) ? ((s == 0) ? m : g_list[s * NTOK + m]) : 0;
    }
    __syncthreads();

    auto load_chunk = [&](int st, int k0) {
        uint32_t base = sb + SM_TILES + st * STAGE_BYTES;
#pragma unroll
        for (int i = 0; i < 8; i++) {   // A: 128 rows x 8 segs = 1024 cp.async
            int id = i * 128 + t;
            int row = id >> 3, seg = id & 7;
            uint32_t d = base + OFF_A + row * RSBA + seg * 16;
            size_t aoff = (size_t)toks[row] * DDIM + k0 + seg * 8;
            cpa16(d, g_xa + aoff);
        }
#pragma unroll
        for (int i = 0; i < 8; i++) {   // B: 64 k-rows x 16 segs = 1024 cp.async
            int id = i * 128 + t;
            int row = id >> 4, seg = id & 15;
            uint32_t d = base + OFF_B + row * RSBB + seg * 16;
            size_t boff = ((size_t)s * DDIM + k0 + row) * HDIM + n0 + seg * 8;
            cpa16(d, g_w1 + boff);
        }
        CPA_COMMIT();
    };

    float acc[4][8][4];
#pragma unroll
    for (int mi = 0; mi < 4; mi++)
#pragma unroll
        for (int ni = 0; ni < 8; ni++)
#pragma unroll
            for (int q = 0; q < 4; q++) acc[mi][ni][q] = 0.f;

    const int CH = DDIM / 64;   // 8
    load_chunk(0, 0);
    for (int c = 0; c < CH; c++) {
        CPA_WAIT0();
        __syncthreads();
        if (c + 1 < CH) load_chunk((c + 1) & 1, (c + 1) * 64);
        gemm_compute_chunk(sb + SM_TILES + (c & 1) * STAGE_BYTES, wm, wn, lane, acc);
    }

    // epilogue: bias + relu -> fp16
    const float* bp = b1 + (size_t)s * HDIM;
#pragma unroll
    for (int mi = 0; mi < 4; mi++) {
        int mA = m0 + wm * 64 + mi * 16 + (lane >> 2);
        int mB = mA + 8;
        size_t rA = ((size_t)s * NTOK + mA) * HDIM;
        size_t rB = ((size_t)s * NTOK + mB) * HDIM;
        bool vA = mA < cnt, vB = mB < cnt;
#pragma unroll
        for (int ni = 0; ni < 8; ni++) {
            int col = n0 + wn * 64 + ni * 8 + 2 * (lane & 3);
            float bc0 = __ldg(bp + col), bc1 = __ldg(bp + col + 1);
            if (vA) {
                float v0 = fmaxf(acc[mi][ni][0] + bc0, 0.f);
                float v1 = fmaxf(acc[mi][ni][1] + bc1, 0.f);
                *(uint32_t*)(g_ha + rA + col) = pack2h(__float2half(v0), __float2half(v1));
            }
            if (vB) {
                float v0 = fmaxf(acc[mi][ni][2] + bc0, 0.f);
                float v1 = fmaxf(acc[mi][ni][3] + bc1, 0.f);
                *(uint32_t*)(g_ha + rB + col) = pack2h(__float2half(v0), __float2half(v1));
            }
        }
    }
}

// ================= GEMM 2: Y = scale * (H @ W2[e] + b2[e]) =================
__global__ void __launch_bounds__(128, 2) k_gemm2(const float* __restrict__ b2,
                                                  const float* __restrict__ fw) {
    int s = blockIdx.z;
    int cnt = (s == 0) ? NTOK : g_cnt[s];
    int m0 = blockIdx.x * BM;
    if (m0 >= cnt) return;
    int n0 = blockIdx.y * 128;

    extern __shared__ char smem[];
    uint32_t sb = smem_u32(smem);
    int t = threadIdx.x;
    int wid = t >> 5, lane = t & 31;
    int wm = wid >> 1, wn = wid & 1;
    float* scl = (float*)smem;

    {
        int m = m0 + t;
        scl[t] = (m < cnt) ? ((s == 0) ? BETA_FIXED * fw[0] : g_scale[s * NTOK + m]) : 0.f;
    }
    __syncthreads();

    auto load_chunk = [&](int st, int k0) {
        uint32_t base = sb + SM_TILES + st * STAGE_BYTES;
#pragma unroll
        for (int i = 0; i < 8; i++) {
            int id = i * 128 + t;
            int row = id >> 3, seg = id & 7;
            uint32_t d = base + OFF_A + row * RSBA + seg * 16;
            size_t aoff = ((size_t)s * NTOK + m0 + row) * HDIM + k0 + seg * 8;
            cpa16(d, g_ha + aoff);
        }
#pragma unroll
        for (int i = 0; i < 8; i++) {
            int id = i * 128 + t;
            int row = id >> 4, seg = id & 15;
            uint32_t d = base + OFF_B + row * RSBB + seg * 16;
            size_t boff = ((size_t)s * HDIM + k0 + row) * DDIM + n0 + seg * 8;
            cpa16(d, g_w2 + boff);
        }
        CPA_COMMIT();
    };

    float acc[4][8][4];
#pragma unroll
    for (int mi = 0; mi < 4; mi++)
#pragma unroll
        for (int ni = 0; ni < 8; ni++)
#pragma unroll
            for (int q = 0; q < 4; q++) acc[mi][ni][q] = 0.f;

    const int CH = HDIM / 64;   // 32
    load_chunk(0, 0);
    for (int c = 0; c < CH; c++) {
        CPA_WAIT0();
        __syncthreads();
        if (c + 1 < CH) load_chunk((c + 1) & 1, (c + 1) * 64);
        gemm_compute_chunk(sb + SM_TILES + (c & 1) * STAGE_BYTES, wm, wn, lane, acc);
    }

    // epilogue: (acc + bias) * scale, fp32 store
    const float* bp = b2 + (size_t)s * DDIM;
#pragma unroll
    for (int mi = 0; mi < 4; mi++) {
        int mloc = wm * 64 + mi * 16 + (lane >> 2);
        int mA = m0 + mloc, mB = mA + 8;
        float scA = scl[mloc], scB = scl[mloc + 8];
        size_t rA = ((size_t)s * NTOK + mA) * DDIM;
        size_t rB = ((size_t)s * NTOK + mB) * DDIM;
        bool vA = mA < cnt, vB = mB < cnt;
#pragma unroll
        for (int ni = 0; ni < 8; ni++) {
            int col = n0 + wn * 64 + ni * 8 + 2 * (lane & 3);
            float bc0 = __ldg(bp + col), bc1 = __ldg(bp + col + 1);
            if (vA) {
                float2 v;
                v.x = (acc[mi][ni][0] + bc0) * scA;
                v.y = (acc[mi][ni][1] + bc1) * scA;
                *(float2*)(g_Y + rA + col) = v;
            }
            if (vB) {
                float2 v;
                v.x = (acc[mi][ni][2] + bc0) * scB;
                v.y = (acc[mi][ni][3] + bc1) * scB;
                *(float2*)(g_Y + rB + col) = v;
            }
        }
    }
}

// ================= combine (+ fused aux losses, + counter re-zero) =================
__global__ void k_combine(float* __restrict__ out, long out_size) {
    int n = blockIdx.x;
    int t = threadIdx.x;
    if (n == 0 && t == 0) {
        float lbl = 0.f, ent = 0.f;
#pragma unroll
        for (int j = 0; j < NC; j++) {
            float imp = g_imp[j] / (float)NTOK;
            float d = imp - (1.0f / NC);
            lbl += d * d;
            ent -= imp * logf(fmaxf(imp, 1e-8f));
        }
        lbl *= (1.0f / NC);
        long base = (long)NTOK * DDIM;
        if (base < out_size)     out[base]     = lbl;
        if (base + 1 < out_size) out[base + 1] = ent;
#pragma unroll
        for (int j = 0; j < NC; j++) g_imp[j] = 0.f;
#pragma unroll
        for (int j = 0; j < NEXP; j++) g_cnt[j] = 0;
    }
    const float4* y0 = (const float4*)(g_Y + (size_t)n * DDIM);
    int pA = g_pos[2 * n], pB = g_pos[2 * n + 1];
    const float4* yA = (const float4*)(g_Y + (size_t)pA * DDIM);
    const float4* yB = (const float4*)(g_Y + (size_t)pB * DDIM);
    float4 a = y0[t], b = yA[t], c = yB[t];
    float4 r;
    r.x = a.x + b.x + c.x;
    r.y = a.y + b.y + c.y;
    r.z = a.z + b.z + c.z;
    r.w = a.w + b.w + c.w;
    ((float4*)(out + (size_t)n * DDIM))[t] = r;
}

// ================= launch =================
extern "C" void kernel_launch(void* const* d_in, const int* in_sizes, int n_in,
                              void* d_out, int out_size) {
    const float* x  = (const float*)d_in[0];
    const float* rW = (const float*)d_in[1];
    const float* rb = (const float*)d_in[2];
    const float* W1 = (const float*)d_in[3];
    const float* b1 = (const float*)d_in[4];
    const float* W2 = (const float*)d_in[5];
    const float* b2 = (const float*)d_in[6];
    const float* fw = (const float*)d_in[7];
    float* out = (float*)d_out;
    long osz = (long)out_size;

    cudaFuncSetAttribute(k_gemm1, cudaFuncAttributeMaxDynamicSharedMemorySize, SMEM_BYTES);
    cudaFuncSetAttribute(k_gemm2, cudaFuncAttributeMaxDynamicSharedMemorySize, SMEM_BYTES);

    k_router<<<NTOK / 8, 256>>>(x, rW, rb, out, osz);
    k_cvt_w<<<(W1_ELEMS + W2_ELEMS) / 4 / 256, 256>>>((const float4*)W1, (const float4*)W2);
    k_gemm1<<<dim3(NTOK / BM, 16, 8), 128, SMEM_BYTES>>>(b1);
    k_gemm2<<<dim3(NTOK / BM, 4, 8), 128, SMEM_BYTES>>>(b2, fw);
    k_combine<<<NTOK, 128>>>(out, osz);
}

// round 12
// speedup vs baseline: 1.2141x; 1.0580x over previous
#include <cuda_runtime.h>
#include <cuda_fp16.h>
#include <math.h>
#include <cstdint>

#define NTOK 4096
#define DDIM 512
#define HDIM 2048
#define NEXP 8
#define NC 7
#define BETA_FIXED (1.0f/3.0f)
#define BETA_DYN   (2.0f/3.0f)

// ================= scratch (static device globals) =================
__device__ __half g_xa[NTOK * DDIM];                 // activations fp16
__device__ __half g_w1[NEXP * DDIM * HDIM];          // [E][D][H] fp16
__device__ __half g_w2[NEXP * HDIM * DDIM];          // [E][H][D] fp16
__device__ __half g_ha[(size_t)NEXP * NTOK * HDIM];  // hidden fp16
__device__ float g_Y[(size_t)NEXP * NTOK * DDIM];
__device__ int   g_list[NEXP * NTOK];
__device__ float g_scale[NEXP * NTOK];
__device__ int   g_pos[NTOK * 2];
__device__ int   g_cnt[NEXP];    // zero at module load; k_combine re-zeroes after use
__device__ float g_imp[NC];      // idem

// ================= helpers =================
__device__ __forceinline__ uint32_t smem_u32(const void* p) {
    uint32_t a;
    asm("{ .reg .u64 t; cvta.to.shared.u64 t, %1; cvt.u32.u64 %0, t; }" : "=r"(a) : "l"(p));
    return a;
}
__device__ __forceinline__ void cpa16(uint32_t dst, const void* src) {
    asm volatile("cp.async.cg.shared.global [%0], [%1], 16;" :: "r"(dst), "l"(src));
}
#define CPA_COMMIT() asm volatile("cp.async.commit_group;" ::: "memory")
#define CPA_WAIT1()  asm volatile("cp.async.wait_group 1;" ::: "memory")

__device__ __forceinline__ void ldm_x4(uint32_t addr, uint32_t* r) {
    asm volatile("ldmatrix.sync.aligned.m8n8.x4.shared.b16 {%0,%1,%2,%3}, [%4];"
        : "=r"(r[0]), "=r"(r[1]), "=r"(r[2]), "=r"(r[3]) : "r"(addr));
}
__device__ __forceinline__ void ldm_x4t(uint32_t addr, uint32_t* r) {
    asm volatile("ldmatrix.sync.aligned.m8n8.x4.trans.shared.b16 {%0,%1,%2,%3}, [%4];"
        : "=r"(r[0]), "=r"(r[1]), "=r"(r[2]), "=r"(r[3]) : "r"(addr));
}
__device__ __forceinline__ void mma16816(float* c, const uint32_t* a, uint32_t b0, uint32_t b1) {
    asm volatile("mma.sync.aligned.m16n8k16.row.col.f32.f16.f16.f32 "
        "{%0,%1,%2,%3}, {%4,%5,%6,%7}, {%8,%9}, {%0,%1,%2,%3};"
        : "+f"(c[0]), "+f"(c[1]), "+f"(c[2]), "+f"(c[3])
        : "r"(a[0]), "r"(a[1]), "r"(a[2]), "r"(a[3]), "r"(b0), "r"(b1));
}
__device__ __forceinline__ uint32_t pack2h(__half a, __half b) {
    return ((uint32_t)__half_as_ushort(b) << 16) | __half_as_ushort(a);
}

// smem per stage:
//   A: 128 m-rows x 64 fp16 k  (128B data + 16B pad = 144B)
//   B: 64 k-rows x 128 fp16 n  (256B data + 16B pad = 272B)
#define RSBA 144
#define RSBB 272
#define BM 128
#define OFF_A  0
#define OFF_B  (BM * RSBA)                       // 18432
#define STAGE_BYTES (BM * RSBA + 64 * RSBB)      // 35840
#define NSTG 3
#define SM_TILES 1024
#define SMEM_BYTES (SM_TILES + NSTG * STAGE_BYTES)   // 108544 -> 2 CTAs/SM (217KB of 228KB)

// ================= fused prep: router (+x->fp16) | weight fp32->fp16 =========
#define RTR_BLOCKS (NTOK / 8)            // 512
#define W1_ELEMS (NEXP * DDIM * HDIM)
#define W2_ELEMS (NEXP * HDIM * DDIM)
#define CVT_BLOCKS ((W1_ELEMS + W2_ELEMS) / 4 / 256)   // 16384

__global__ void k_prep(const float* __restrict__ x,
                       const float* __restrict__ rW,
                       const float* __restrict__ rb,
                       const float4* __restrict__ W1,
                       const float4* __restrict__ W2,
                       float* __restrict__ out, long out_size) {
    int t = threadIdx.x;
    if (blockIdx.x >= RTR_BLOCKS) {
        // ---- weight conversion path ----
        int i = (blockIdx.x - RTR_BLOCKS) * blockDim.x + t;   // over float4s
        const int T1 = W1_ELEMS / 4;
        float4 v;
        uint2 p;
        if (i < T1) {
            v = W1[i];
            p.x = pack2h(__float2half(v.x), __float2half(v.y));
            p.y = pack2h(__float2half(v.z), __float2half(v.w));
            ((uint2*)g_w1)[i] = p;
        } else {
            int j = i - T1;
            v = W2[j];
            p.x = pack2h(__float2half(v.x), __float2half(v.y));
            p.y = pack2h(__float2half(v.z), __float2half(v.w));
            ((uint2*)g_w2)[j] = p;
        }
        return;
    }

    // ---- router path ----
    __shared__ float imp_s[NC];
    if (t < NC) imp_s[t] = 0.f;
    __syncthreads();

    int w = t >> 5, lane = t & 31;
    int n = blockIdx.x * 8 + w;

    float acc[NC];
#pragma unroll
    for (int j = 0; j < NC; j++) acc[j] = 0.f;

    const float* xr = x + (size_t)n * DDIM;
    __half* xout = g_xa + (size_t)n * DDIM;
    for (int k = lane; k < DDIM; k += 32) {
        float xv = xr[k];
        xout[k] = __float2half(xv);          // fused conversion
        const float* wr = rW + (size_t)k * NC;
#pragma unroll
        for (int j = 0; j < NC; j++) acc[j] += xv * wr[j];
    }
#pragma unroll
    for (int j = 0; j < NC; j++) {
#pragma unroll
        for (int off = 16; off > 0; off >>= 1)
            acc[j] += __shfl_xor_sync(0xffffffffu, acc[j], off);
        acc[j] += rb[j];
    }

    if (lane == 0) {
        float m = acc[0];
#pragma unroll
        for (int j = 1; j < NC; j++) m = fmaxf(m, acc[j]);
        float p[NC], s = 0.f;
#pragma unroll
        for (int j = 0; j < NC; j++) { p[j] = __expf(acc[j] - m); s += p[j]; }
        float inv = 1.f / s;
#pragma unroll
        for (int j = 0; j < NC; j++) atomicAdd(&imp_s[j], p[j] * inv);

        int i1 = 0;
#pragma unroll
        for (int j = 1; j < NC; j++) if (acc[j] > acc[i1]) i1 = j;
        int i2 = (i1 == 0) ? 1 : 0;
#pragma unroll
        for (int j = 0; j < NC; j++) if (j != i1 && acc[j] > acc[i2]) i2 = j;

        float e2 = __expf(acc[i2] - acc[i1]);
        float den = 1.f / (1.f + e2);
        float gA = den, gB = e2 * den;

        int eA = i1 + 1, eB = i2 + 1;
        int rA = atomicAdd(&g_cnt[eA], 1);
        int rB = atomicAdd(&g_cnt[eB], 1);
        int rowA = eA * NTOK + rA;
        int rowB = eB * NTOK + rB;
        g_list[rowA] = n;  g_list[rowB] = n;
        g_scale[rowA] = BETA_DYN * gA;
        g_scale[rowB] = BETA_DYN * gB;
        g_pos[2 * n]     = rowA;
        g_pos[2 * n + 1] = rowB;

        long selbase = (long)NTOK * DDIM + 2;
        if (selbase + 2 * (long)NTOK <= out_size) {
            out[selbase + 2 * n]     = (float)eA;
            out[selbase + 2 * n + 1] = (float)eB;
        }
    }
    __syncthreads();
    if (t < NC) atomicAdd(&g_imp[t], imp_s[t]);
}

// ================= shared GEMM compute core =================
// block 128x128, 4 warps (2Mx2N), warp tile 64x64, k-chunk 64 (4 x k16)
// A: [m][k] rows, non-trans ldmatrix.  B: [k][n] rows, trans ldmatrix.
__device__ __forceinline__ void gemm_compute_chunk(
    uint32_t tb, int wm, int wn, int lane, float acc[4][8][4])
{
    uint32_t a_row = (uint32_t)((lane & 7) + ((lane >> 3) & 1) * 8);
    uint32_t a_kh  = (uint32_t)(lane >> 4);
    uint32_t a_base = tb + OFF_A + (wm * 64 + a_row) * RSBA + a_kh * 16;

    uint32_t grp = (uint32_t)(lane >> 3), sub = (uint32_t)(lane & 7);
    uint32_t k_loc = (grp & 1) * 8 + sub;           // k row within k16
    uint32_t n_loc = (grp >> 1) * 8;                // n col within 16-col group
    uint32_t b_base = tb + OFF_B + k_loc * RSBB + (wn * 64 + n_loc) * 2;

#pragma unroll
    for (int kk = 0; kk < 4; kk++) {
        uint32_t ah[4][4];
#pragma unroll
        for (int mf = 0; mf < 4; mf++)
            ldm_x4(a_base + mf * 16 * RSBA + kk * 32, ah[mf]);
#pragma unroll
        for (int p = 0; p < 4; p++) {
            uint32_t br[4];
            ldm_x4t(b_base + kk * 16 * RSBB + p * 32, br);
#pragma unroll
            for (int q = 0; q < 2; q++) {
                int ni = p * 2 + q;
#pragma unroll
                for (int mi = 0; mi < 4; mi++)
                    mma16816(acc[mi][ni], ah[mi], br[2 * q], br[2 * q + 1]);
            }
        }
    }
}

// ================= GEMM 1: H = relu(Xg @ W1[e] + b1[e]) -> fp16 =================
__global__ void __launch_bounds__(128, 2) k_gemm1(const float* __restrict__ b1) {
    int s = blockIdx.z;
    int cnt = (s == 0) ? NTOK : g_cnt[s];
    int m0 = blockIdx.x * BM;
    if (m0 >= cnt) return;
    int n0 = blockIdx.y * 128;

    extern __shared__ char smem[];
    uint32_t sb = smem_u32(smem);
    int t = threadIdx.x;
    int wid = t >> 5, lane = t & 31;
    int wm = wid >> 1, wn = wid & 1;
    int* toks = (int*)smem;

    {
        int m = m0 + t;
        toks[t] = (m < cnt) ? ((s == 0) ? m : g_list[s * NTOK + m]) : 0;
    }
    __syncthreads();

    auto load_chunk = [&](int st, int k0) {
        uint32_t base = sb + SM_TILES + st * STAGE_BYTES;
#pragma unroll
        for (int i = 0; i < 8; i++) {   // A: 128 rows x 8 segs = 1024 cp.async
            int id = i * 128 + t;
            int row = id >> 3, seg = id & 7;
            uint32_t d = base + OFF_A + row * RSBA + seg * 16;
            size_t aoff = (size_t)toks[row] * DDIM + k0 + seg * 8;
            cpa16(d, g_xa + aoff);
        }
#pragma unroll
        for (int i = 0; i < 8; i++) {   // B: 64 k-rows x 16 segs = 1024 cp.async
            int id = i * 128 + t;
            int row = id >> 4, seg = id & 15;
            uint32_t d = base + OFF_B + row * RSBB + seg * 16;
            size_t boff = ((size_t)s * DDIM + k0 + row) * HDIM + n0 + seg * 8;
            cpa16(d, g_w1 + boff);
        }
        CPA_COMMIT();
    };

    float acc[4][8][4];
#pragma unroll
    for (int mi = 0; mi < 4; mi++)
#pragma unroll
        for (int ni = 0; ni < 8; ni++)
#pragma unroll
            for (int q = 0; q < 4; q++) acc[mi][ni][q] = 0.f;

    const int CH = DDIM / 64;   // 8
    load_chunk(0, 0);
    load_chunk(1, 64);
    for (int c = 0; c < CH; c++) {
        CPA_WAIT1();
        __syncthreads();
        if (c + 2 < CH) load_chunk((c + 2) % NSTG, (c + 2) * 64);
        else            CPA_COMMIT();   // keep group accounting uniform
        gemm_compute_chunk(sb + SM_TILES + (c % NSTG) * STAGE_BYTES, wm, wn, lane, acc);
    }

    // epilogue: bias + relu -> fp16
    const float* bp = b1 + (size_t)s * HDIM;
#pragma unroll
    for (int mi = 0; mi < 4; mi++) {
        int mA = m0 + wm * 64 + mi * 16 + (lane >> 2);
        int mB = mA + 8;
        size_t rA = ((size_t)s * NTOK + mA) * HDIM;
        size_t rB = ((size_t)s * NTOK + mB) * HDIM;
        bool vA = mA < cnt, vB = mB < cnt;
#pragma unroll
        for (int ni = 0; ni < 8; ni++) {
            int col = n0 + wn * 64 + ni * 8 + 2 * (lane & 3);
            float bc0 = __ldg(bp + col), bc1 = __ldg(bp + col + 1);
            if (vA) {
                float v0 = fmaxf(acc[mi][ni][0] + bc0, 0.f);
                float v1 = fmaxf(acc[mi][ni][1] + bc1, 0.f);
                *(uint32_t*)(g_ha + rA + col) = pack2h(__float2half(v0), __float2half(v1));
            }
            if (vB) {
                float v0 = fmaxf(acc[mi][ni][2] + bc0, 0.f);
                float v1 = fmaxf(acc[mi][ni][3] + bc1, 0.f);
                *(uint32_t*)(g_ha + rB + col) = pack2h(__float2half(v0), __float2half(v1));
            }
        }
    }
}

// ================= GEMM 2: Y = scale * (H @ W2[e] + b2[e]) =================
__global__ void __launch_bounds__(128, 2) k_gemm2(const float* __restrict__ b2,
                                                  const float* __restrict__ fw) {
    int s = blockIdx.z;
    int cnt = (s == 0) ? NTOK : g_cnt[s];
    int m0 = blockIdx.x * BM;
    if (m0 >= cnt) return;
    int n0 = blockIdx.y * 128;

    extern __shared__ char smem[];
    uint32_t sb = smem_u32(smem);
    int t = threadIdx.x;
    int wid = t >> 5, lane = t & 31;
    int wm = wid >> 1, wn = wid & 1;
    float* scl = (float*)smem;

    {
        int m = m0 + t;
        scl[t] = (m < cnt) ? ((s == 0) ? BETA_FIXED * fw[0] : g_scale[s * NTOK + m]) : 0.f;
    }
    __syncthreads();

    auto load_chunk = [&](int st, int k0) {
        uint32_t base = sb + SM_TILES + st * STAGE_BYTES;
#pragma unroll
        for (int i = 0; i < 8; i++) {
            int id = i * 128 + t;
            int row = id >> 3, seg = id & 7;
            uint32_t d = base + OFF_A + row * RSBA + seg * 16;
            size_t aoff = ((size_t)s * NTOK + m0 + row) * HDIM + k0 + seg * 8;
            cpa16(d, g_ha + aoff);
        }
#pragma unroll
        for (int i = 0; i < 8; i++) {
            int id = i * 128 + t;
            int row = id >> 4, seg = id & 15;
            uint32_t d = base + OFF_B + row * RSBB + seg * 16;
            size_t boff = ((size_t)s * HDIM + k0 + row) * DDIM + n0 + seg * 8;
            cpa16(d, g_w2 + boff);
        }
        CPA_COMMIT();
    };

    float acc[4][8][4];
#pragma unroll
    for (int mi = 0; mi < 4; mi++)
#pragma unroll
        for (int ni = 0; ni < 8; ni++)
#pragma unroll
            for (int q = 0; q < 4; q++) acc[mi][ni][q] = 0.f;

    const int CH = HDIM / 64;   // 32
    load_chunk(0, 0);
    load_chunk(1, 64);
    for (int c = 0; c < CH; c++) {
        CPA_WAIT1();
        __syncthreads();
        if (c + 2 < CH) load_chunk((c + 2) % NSTG, (c + 2) * 64);
        else            CPA_COMMIT();
        gemm_compute_chunk(sb + SM_TILES + (c % NSTG) * STAGE_BYTES, wm, wn, lane, acc);
    }

    // epilogue: (acc + bias) * scale, fp32 store
    const float* bp = b2 + (size_t)s * DDIM;
#pragma unroll
    for (int mi = 0; mi < 4; mi++) {
        int mloc = wm * 64 + mi * 16 + (lane >> 2);
        int mA = m0 + mloc, mB = mA + 8;
        float scA = scl[mloc], scB = scl[mloc + 8];
        size_t rA = ((size_t)s * NTOK + mA) * DDIM;
        size_t rB = ((size_t)s * NTOK + mB) * DDIM;
        bool vA = mA < cnt, vB = mB < cnt;
#pragma unroll
        for (int ni = 0; ni < 8; ni++) {
            int col = n0 + wn * 64 + ni * 8 + 2 * (lane & 3);
            float bc0 = __ldg(bp + col), bc1 = __ldg(bp + col + 1);
            if (vA) {
                float2 v;
                v.x = (acc[mi][ni][0] + bc0) * scA;
                v.y = (acc[mi][ni][1] + bc1) * scA;
                *(float2*)(g_Y + rA + col) = v;
            }
            if (vB) {
                float2 v;
                v.x = (acc[mi][ni][2] + bc0) * scB;
                v.y = (acc[mi][ni][3] + bc1) * scB;
                *(float2*)(g_Y + rB + col) = v;
            }
        }
    }
}

// ================= combine (+ fused aux losses, + counter re-zero) =================
__global__ void k_combine(float* __restrict__ out, long out_size) {
    int n = blockIdx.x;
    int t = threadIdx.x;
    if (n == 0 && t == 0) {
        float lbl = 0.f, ent = 0.f;
#pragma unroll
        for (int j = 0; j < NC; j++) {
            float imp = g_imp[j] / (float)NTOK;
            float d = imp - (1.0f / NC);
            lbl += d * d;
            ent -= imp * logf(fmaxf(imp, 1e-8f));
        }
        lbl *= (1.0f / NC);
        long base = (long)NTOK * DDIM;
        if (base < out_size)     out[base]     = lbl;
        if (base + 1 < out_size) out[base + 1] = ent;
#pragma unroll
        for (int j = 0; j < NC; j++) g_imp[j] = 0.f;
#pragma unroll
        for (int j = 0; j < NEXP; j++) g_cnt[j] = 0;
    }
    const float4* y0 = (const float4*)(g_Y + (size_t)n * DDIM);
    int pA = g_pos[2 * n], pB = g_pos[2 * n + 1];
    const float4* yA = (const float4*)(g_Y + (size_t)pA * DDIM);
    const float4* yB = (const float4*)(g_Y + (size_t)pB * DDIM);
    float4 a = y0[t], b = yA[t], c = yB[t];
    float4 r;
    r.x = a.x + b.x + c.x;
    r.y = a.y + b.y + c.y;
    r.z = a.z + b.z + c.z;
    r.w = a.w + b.w + c.w;
    ((float4*)(out + (size_t)n * DDIM))[t] = r;
}

// ================= launch =================
extern "C" void kernel_launch(void* const* d_in, const int* in_sizes, int n_in,
                              void* d_out, int out_size) {
    const float* x  = (const float*)d_in[0];
    const float* rW = (const float*)d_in[1];
    const float* rb = (const float*)d_in[2];
    const float* W1 = (const float*)d_in[3];
    const float* b1 = (const float*)d_in[4];
    const float* W2 = (const float*)d_in[5];
    const float* b2 = (const float*)d_in[6];
    const float* fw = (const float*)d_in[7];
    float* out = (float*)d_out;
    long osz = (long)out_size;

    cudaFuncSetAttribute(k_gemm1, cudaFuncAttributeMaxDynamicSharedMemorySize, SMEM_BYTES);
    cudaFuncSetAttribute(k_gemm2, cudaFuncAttributeMaxDynamicSharedMemorySize, SMEM_BYTES);

    k_prep<<<RTR_BLOCKS + CVT_BLOCKS, 256>>>(x, rW, rb,
                                             (const float4*)W1, (const float4*)W2,
                                             out, osz);
    k_gemm1<<<dim3(NTOK / BM, 16, 8), 128, SMEM_BYTES>>>(b1);
    k_gemm2<<<dim3(NTOK / BM, 4, 8), 128, SMEM_BYTES>>>(b2, fw);
    k_combine<<<NTOK, 128>>>(out, osz);
}